// round 2
// baseline (speedup 1.0000x reference)
#include <cuda_runtime.h>
#include <cuda_fp16.h>
#include <mma.h>

using namespace nvcuda;

#define TOKENS   200704      // 4096 * 49
#define DIMC     512
#define QKV_N    1536
#define SS       49
#define NHEADS   16
#define HD       32
#define NWG      64

__device__ float g_qkv[(size_t)TOKENS * QKV_N];   // 1.23 GB scratch
__device__ float g_attn[(size_t)TOKENS * DIMC];   // 411 MB scratch

// ---------------- split-fp16 wmma GEMM: C = A(MxK) @ B(KxN) + bias ----------
#define BM 128
#define BN 128
#define BK 32

struct GemmSmem {
    union {
        struct {
            half Ah[BM][BK];
            half Al[BM][BK];
            half Bh[BK][BN];
            half Bl[BK][BN];
        } t;                       // 32768 B
        float stage[8][16 * 68];   // 34816 B (epilogue staging, per warp)
    } u;
    float bias_s[BN];
};

__global__ __launch_bounds__(256) void gemm_split_kernel(
    const float* __restrict__ A, const float* __restrict__ B,
    const float* __restrict__ bias, float* __restrict__ C,
    int M, int N, int K)
{
    __shared__ GemmSmem sm;
    const int tid    = threadIdx.x;
    const int wid    = tid >> 5;
    const int lane   = tid & 31;
    const int warp_m = wid & 3;    // 0..3  -> rows  warp_m*32
    const int warp_n = wid >> 2;   // 0..1  -> cols  warp_n*64
    const int m0 = blockIdx.y * BM;
    const int n0 = blockIdx.x * BN;

    if (tid < BN) sm.bias_s[tid] = bias[n0 + tid];

    wmma::fragment<wmma::accumulator, 16, 16, 16, float> acc[2][4];
#pragma unroll
    for (int i = 0; i < 2; i++)
#pragma unroll
        for (int j = 0; j < 4; j++)
            wmma::fill_fragment(acc[i][j], 0.0f);

    for (int kt = 0; kt < K; kt += BK) {
        // ---- load + split A tile (128 x 32) ----
#pragma unroll
        for (int it = 0; it < 4; it++) {
            int i  = tid + it * 256;
            int r  = i >> 3;
            int c4 = (i & 7) << 2;
            float4 f = *(const float4*)(A + (size_t)(m0 + r) * K + kt + c4);
            half hx = __float2half_rn(f.x), hy = __float2half_rn(f.y);
            half hz = __float2half_rn(f.z), hw = __float2half_rn(f.w);
            half lx = __float2half_rn(f.x - __half2float(hx));
            half ly = __float2half_rn(f.y - __half2float(hy));
            half lz = __float2half_rn(f.z - __half2float(hz));
            half lw = __float2half_rn(f.w - __half2float(hw));
            *(half2*)&sm.u.t.Ah[r][c4]     = __halves2half2(hx, hy);
            *(half2*)&sm.u.t.Ah[r][c4 + 2] = __halves2half2(hz, hw);
            *(half2*)&sm.u.t.Al[r][c4]     = __halves2half2(lx, ly);
            *(half2*)&sm.u.t.Al[r][c4 + 2] = __halves2half2(lz, lw);
        }
        // ---- load + split B tile (32 x 128) ----
#pragma unroll
        for (int it = 0; it < 4; it++) {
            int i  = tid + it * 256;
            int r  = i >> 5;
            int c4 = (i & 31) << 2;
            float4 f = *(const float4*)(B + (size_t)(kt + r) * N + n0 + c4);
            half hx = __float2half_rn(f.x), hy = __float2half_rn(f.y);
            half hz = __float2half_rn(f.z), hw = __float2half_rn(f.w);
            half lx = __float2half_rn(f.x - __half2float(hx));
            half ly = __float2half_rn(f.y - __half2float(hy));
            half lz = __float2half_rn(f.z - __half2float(hz));
            half lw = __float2half_rn(f.w - __half2float(hw));
            *(half2*)&sm.u.t.Bh[r][c4]     = __halves2half2(hx, hy);
            *(half2*)&sm.u.t.Bh[r][c4 + 2] = __halves2half2(hz, hw);
            *(half2*)&sm.u.t.Bl[r][c4]     = __halves2half2(lx, ly);
            *(half2*)&sm.u.t.Bl[r][c4 + 2] = __halves2half2(lz, lw);
        }
        __syncthreads();

#pragma unroll
        for (int kk = 0; kk < BK; kk += 16) {
            wmma::fragment<wmma::matrix_a, 16, 16, 16, half, wmma::row_major> ah[2], al[2];
#pragma unroll
            for (int im = 0; im < 2; im++) {
                wmma::load_matrix_sync(ah[im], &sm.u.t.Ah[warp_m * 32 + im * 16][kk], BK);
                wmma::load_matrix_sync(al[im], &sm.u.t.Al[warp_m * 32 + im * 16][kk], BK);
            }
#pragma unroll
            for (int jn = 0; jn < 4; jn++) {
                wmma::fragment<wmma::matrix_b, 16, 16, 16, half, wmma::row_major> bh, bl;
                wmma::load_matrix_sync(bh, &sm.u.t.Bh[kk][warp_n * 64 + jn * 16], BN);
                wmma::load_matrix_sync(bl, &sm.u.t.Bl[kk][warp_n * 64 + jn * 16], BN);
#pragma unroll
                for (int im = 0; im < 2; im++) {
                    wmma::mma_sync(acc[im][jn], ah[im], bh, acc[im][jn]);
                    wmma::mma_sync(acc[im][jn], al[im], bh, acc[im][jn]);
                    wmma::mma_sync(acc[im][jn], ah[im], bl, acc[im][jn]);
                }
            }
        }
        __syncthreads();
    }

    // ---- epilogue: stage through shared, add bias, write fp32 ----
    float* stg = sm.u.stage[wid];
#pragma unroll
    for (int im = 0; im < 2; im++) {
#pragma unroll
        for (int jn = 0; jn < 4; jn++)
            wmma::store_matrix_sync(&stg[jn * 16], acc[im][jn], 68, wmma::mem_row_major);
        __syncwarp();
        int row_base = m0 + warp_m * 32 + im * 16;
        int col_base = n0 + warp_n * 64;
#pragma unroll
        for (int e = 0; e < 32; e++) {
            int idx = lane + e * 32;
            int r = idx >> 6, c = idx & 63;
            C[(size_t)(row_base + r) * N + col_base + c] =
                stg[r * 68 + c] + sm.bias_s[warp_n * 64 + c];
        }
        __syncwarp();
    }
}

// ---------------- fused window attention (fp32) ----------------------------
__global__ __launch_bounds__(256) void attn_kernel(
    const float* __restrict__ qkv, const float* __restrict__ mask,
    const float* __restrict__ bias_table, const int* __restrict__ rel_index,
    float* __restrict__ attn_out)
{
    __shared__ float qs[SS][HD + 1];
    __shared__ float ks[SS][HD + 1];
    __shared__ float vs[SS][HD + 1];
    __shared__ float ps[SS][SS + 1];

    const int b   = blockIdx.x;
    const int h   = blockIdx.y;
    const int tid = threadIdx.x;
    const float scale = 0.17677669529663687f;  // 32^-0.5

    // load q/k/v [49,32] for this (window, head)
    for (int i = tid; i < SS * HD; i += 256) {
        int s = i >> 5, d = i & 31;
        size_t row = (size_t)(b * SS + s) * QKV_N;
        qs[s][d] = qkv[row + h * HD + d] * scale;
        ks[s][d] = qkv[row + DIMC + h * HD + d];
        vs[s][d] = qkv[row + 2 * DIMC + h * HD + d];
    }
    __syncthreads();

    // logits + relative-position bias + shift mask
    const int g = b & (NWG - 1);
    const float* mrow = mask + (size_t)g * SS * SS;
    for (int e = tid; e < SS * SS; e += 256) {
        int i = e / SS, j = e - i * SS;
        float acc = 0.f;
#pragma unroll
        for (int d = 0; d < HD; d++) acc += qs[i][d] * ks[j][d];
        acc += bias_table[rel_index[e] * NHEADS + h] + mrow[e];
        ps[i][j] = acc;
    }
    __syncthreads();

    // row softmax: one warp per row
    const int wid = tid >> 5, lane = tid & 31;
    for (int i = wid; i < SS; i += 8) {
        float a0 = ps[i][lane];
        float a1 = (lane < SS - 32) ? ps[i][lane + 32] : -1e30f;
        float m = fmaxf(a0, a1);
#pragma unroll
        for (int off = 16; off > 0; off >>= 1)
            m = fmaxf(m, __shfl_xor_sync(0xffffffffu, m, off));
        float e0 = __expf(a0 - m);
        float e1 = (lane < SS - 32) ? __expf(a1 - m) : 0.f;
        float sum = e0 + e1;
#pragma unroll
        for (int off = 16; off > 0; off >>= 1)
            sum += __shfl_xor_sync(0xffffffffu, sum, off);
        float inv = 1.f / sum;
        ps[i][lane] = e0 * inv;
        if (lane < SS - 32) ps[i][lane + 32] = e1 * inv;
    }
    __syncthreads();

    // attn @ V -> [49,32], scatter into [TOKENS, 512]
    for (int e = tid; e < SS * HD; e += 256) {
        int i = e >> 5, d = e & 31;
        float acc = 0.f;
#pragma unroll
        for (int j = 0; j < SS; j++) acc += ps[i][j] * vs[j][d];
        attn_out[(size_t)(b * SS + i) * DIMC + h * HD + d] = acc;
    }
}

// ---------------- launch ----------------------------------------------------
extern "C" void kernel_launch(void* const* d_in, const int* in_sizes, int n_in,
                              void* d_out, int out_size)
{
    const float* x          = (const float*)d_in[0];
    const float* mask       = (const float*)d_in[1];
    const float* Wqkv       = (const float*)d_in[2];
    const float* bqkv       = (const float*)d_in[3];
    const float* Wproj      = (const float*)d_in[4];
    const float* bproj      = (const float*)d_in[5];
    const float* bias_table = (const float*)d_in[6];
    const int*   rel_index  = (const int*)d_in[7];
    float* out = (float*)d_out;

    float *qkv, *attn;
    cudaGetSymbolAddress((void**)&qkv,  g_qkv);
    cudaGetSymbolAddress((void**)&attn, g_attn);

    // qkv = x @ Wqkv + bqkv      (N-fastest grid for A-tile L2 reuse)
    dim3 g1(QKV_N / BN, TOKENS / BM);
    gemm_split_kernel<<<g1, 256>>>(x, Wqkv, bqkv, qkv, TOKENS, QKV_N, DIMC);

    // fused window attention
    attn_kernel<<<dim3(4096, NHEADS), 256>>>(qkv, mask, bias_table, rel_index, attn);

    // out = attn @ Wproj + bproj
    dim3 g2(DIMC / BN, TOKENS / BM);
    gemm_split_kernel<<<g2, 256>>>(attn, Wproj, bproj, out, TOKENS, DIMC, DIMC);
}

// round 6
// speedup vs baseline: 3.7940x; 3.7940x over previous
#include <cuda_runtime.h>
#include <cuda_fp16.h>
#include <cstdint>

#define TOKENS   200704      // 4096 * 49
#define DIMC     512
#define QKV_N    1536
#define KDIM     512
#define SS       49
#define NHEADS   16
#define HD       32
#define NWG      64

// ---------------- scratch ---------------------------------------------------
__device__ float  g_qkv[(size_t)TOKENS * QKV_N];     // 1.23 GB
__device__ __half g_xh[(size_t)TOKENS * KDIM];       // split A (reused for attn out)
__device__ __half g_xl[(size_t)TOKENS * KDIM];
__device__ __half g_wqh[(size_t)QKV_N * KDIM];       // Wqkv^T hi
__device__ __half g_wql[(size_t)QKV_N * KDIM];
__device__ __half g_wph[(size_t)DIMC * KDIM];        // Wproj^T hi
__device__ __half g_wpl[(size_t)DIMC * KDIM];
__device__ float  g_comb[(size_t)NWG * NHEADS * SS * 52];  // bias+mask, padded rows

// ---------------- asm helpers -----------------------------------------------
__device__ __forceinline__ uint32_t smem_u32(const void* p) {
    uint32_t a;
    asm("{ .reg .u64 t; cvta.to.shared.u64 t, %1; cvt.u32.u64 %0, t; }" : "=r"(a) : "l"(p));
    return a;
}

#define CP16(d, s) asm volatile("cp.async.cg.shared.global [%0], [%1], 16;" :: "r"(d), "l"(s))
#define CP_COMMIT() asm volatile("cp.async.commit_group;" ::: "memory")
#define CP_WAIT1()  asm volatile("cp.async.wait_group 1;" ::: "memory")
#define CP_WAIT0()  asm volatile("cp.async.wait_group 0;" ::: "memory")

#define LDSM4(R, a) asm volatile( \
    "ldmatrix.sync.aligned.m8n8.x4.shared.b16 {%0,%1,%2,%3}, [%4];" \
    : "=r"((R)[0]),"=r"((R)[1]),"=r"((R)[2]),"=r"((R)[3]) : "r"(a))
#define LDSM2(R, a) asm volatile( \
    "ldmatrix.sync.aligned.m8n8.x2.shared.b16 {%0,%1}, [%2];" \
    : "=r"((R)[0]),"=r"((R)[1]) : "r"(a))

#define MMA16816(Cc, Aa, Bb) asm volatile( \
    "mma.sync.aligned.m16n8k16.row.col.f32.f16.f16.f32 " \
    "{%0,%1,%2,%3}, {%4,%5,%6,%7}, {%8,%9}, {%0,%1,%2,%3};" \
    : "+f"((Cc)[0]),"+f"((Cc)[1]),"+f"((Cc)[2]),"+f"((Cc)[3]) \
    : "r"((Aa)[0]),"r"((Aa)[1]),"r"((Aa)[2]),"r"((Aa)[3]), "r"((Bb)[0]),"r"((Bb)[1]))

// ---------------- split kernels ----------------------------------------------
__global__ __launch_bounds__(256) void split_x(const float* __restrict__ in,
                                               __half* __restrict__ oh,
                                               __half* __restrict__ ol)
{
    size_t base = ((size_t)blockIdx.x * 256 + threadIdx.x) * 4;
    float4 f = *(const float4*)(in + base);
    __half hx = __float2half_rn(f.x), hy = __float2half_rn(f.y);
    __half hz = __float2half_rn(f.z), hw = __float2half_rn(f.w);
    __half lx = __float2half_rn(f.x - __half2float(hx));
    __half ly = __float2half_rn(f.y - __half2float(hy));
    __half lz = __float2half_rn(f.z - __half2float(hz));
    __half lw = __float2half_rn(f.w - __half2float(hw));
    __half2 h2[2] = { __halves2half2(hx, hy), __halves2half2(hz, hw) };
    __half2 l2[2] = { __halves2half2(lx, ly), __halves2half2(lz, lw) };
    *(uint2*)(oh + base) = *(uint2*)h2;
    *(uint2*)(ol + base) = *(uint2*)l2;
}

__global__ __launch_bounds__(256) void split_w(const float* __restrict__ in,
                                               __half* __restrict__ oh,
                                               __half* __restrict__ ol, int K, int N)
{
    int t = blockIdx.x * 256 + threadIdx.x;
    if (t >= K * N) return;
    int k = t / N, n = t - k * N;
    float f = in[t];
    __half h = __float2half_rn(f);
    __half l = __float2half_rn(f - __half2float(h));
    oh[(size_t)n * K + k] = h;       // W^T layout [n][k]
    ol[(size_t)n * K + k] = l;
}

// ---------------- comb = bias-gather + mask (padded rows of 52) --------------
__global__ __launch_bounds__(256) void comb_k(const float* __restrict__ mask,
                                              const float* __restrict__ bias_table,
                                              const int* __restrict__ rel_index,
                                              float* __restrict__ comb)
{
    int idx = blockIdx.x * 256 + threadIdx.x;
    const int total = NWG * NHEADS * SS * 52;
    if (idx >= total) return;
    int j = idx % 52;
    int t = idx / 52;
    int i = t % SS;  t /= SS;
    int h = t % NHEADS;
    int g = t / NHEADS;
    float v = 0.f;
    if (j < SS)
        v = bias_table[rel_index[i * SS + j] * NHEADS + h] + mask[((size_t)g * SS + i) * SS + j];
    comb[idx] = v;
}

// ---------------- HMMA split-fp16 GEMM ---------------------------------------
// C[M,N] = (Ah+Al)[M,512] @ (Bh+Bl)[N,512]^T + bias   (3-product expansion)
// Block 128x128, BK=64, 3-stage cp.async, warp tile 64x32 (2x4 warp grid).
#define STAGE_BYTES 65536
#define GEMM_SMEM   (3 * STAGE_BYTES)

__global__ __launch_bounds__(256) void gemm_hmma(
    const __half* __restrict__ Ahp, const __half* __restrict__ Alp,
    const __half* __restrict__ Bhp, const __half* __restrict__ Blp,
    const float* __restrict__ bias, float* __restrict__ C, int N)
{
    extern __shared__ char smem[];
    const uint32_t sb = smem_u32(smem);
    const int tid = threadIdx.x, wid = tid >> 5, lane = tid & 31;
    const int m0 = blockIdx.y * 128, n0 = blockIdx.x * 128;
    const int warp_m = wid & 1, warp_n = wid >> 1;

    float acc[4][4][4];
#pragma unroll
    for (int a = 0; a < 4; a++)
#pragma unroll
        for (int b = 0; b < 4; b++)
#pragma unroll
            for (int c = 0; c < 4; c++) acc[a][b][c] = 0.f;

    // per-lane cp.async coords
    const int cr0 = tid >> 3;        // row for u=0 (increments by 32 per u)
    const int ckc = tid & 7;         // 16B chunk within 128B row

#define LOAD_STAGE(st, ch) do {                                              \
        uint32_t sp_ = sb + (st) * STAGE_BYTES;                              \
        int kt_ = (ch) * 64;                                                 \
        _Pragma("unroll")                                                    \
        for (int u = 0; u < 4; u++) {                                        \
            int r_ = cr0 + u * 32;                                           \
            uint32_t d_ = sp_ + r_ * 128 + (((uint32_t)(ckc ^ (r_ & 7))) << 4); \
            size_t so_ = (size_t)kt_ + ckc * 8;                              \
            CP16(d_,         Ahp + (size_t)(m0 + r_) * KDIM + so_);          \
            CP16(d_ + 16384, Alp + (size_t)(m0 + r_) * KDIM + so_);          \
            CP16(d_ + 32768, Bhp + (size_t)(n0 + r_) * KDIM + so_);          \
            CP16(d_ + 49152, Blp + (size_t)(n0 + r_) * KDIM + so_);          \
        }                                                                    \
    } while (0)

    LOAD_STAGE(0, 0); CP_COMMIT();
    LOAD_STAGE(1, 1); CP_COMMIT();

    // ldmatrix lane geometry
    const int g  = lane >> 3;          // 0..3 (A x4 groups)
    const int lr = lane & 7;
    const int gh = g >> 1;             // A k-half select
    const int lrB = lane & 7, hB = (lane >> 3) & 1;
    const uint32_t aRow = (uint32_t)((warp_m * 64 + (g & 1) * 8 + lr) * 128);
    const uint32_t bRow = (uint32_t)((warp_n * 32 + lrB) * 128);

    for (int c = 0; c < 8; c++) {
        if (c < 7) CP_WAIT1(); else CP_WAIT0();
        __syncthreads();
        if (c + 2 < 8) { LOAD_STAGE((c + 2) % 3, c + 2); CP_COMMIT(); }

        const uint32_t As = sb + (c % 3) * STAGE_BYTES;
        const uint32_t Bs = As + 32768;
#pragma unroll
        for (int ks = 0; ks < 4; ks++) {
            uint32_t ah[4][4], al[4][4], bh[4][2], bl[4][2];
            const uint32_t cA = (uint32_t)(((ks * 2 + gh) ^ lr) << 4);
            const uint32_t cB = (uint32_t)(((ks * 2 + hB) ^ lrB) << 4);
#pragma unroll
            for (int mi = 0; mi < 4; mi++) LDSM4(ah[mi], As + aRow + mi * 2048 + cA);
#pragma unroll
            for (int ni = 0; ni < 4; ni++) {
                LDSM2(bh[ni], Bs + bRow + ni * 1024 + cB);
                LDSM2(bl[ni], Bs + 16384 + bRow + ni * 1024 + cB);
            }
#pragma unroll
            for (int mi = 0; mi < 4; mi++)
#pragma unroll
                for (int ni = 0; ni < 4; ni++) MMA16816(acc[mi][ni], ah[mi], bh[ni]);
#pragma unroll
            for (int mi = 0; mi < 4; mi++) LDSM4(al[mi], As + 16384 + aRow + mi * 2048 + cA);
#pragma unroll
            for (int mi = 0; mi < 4; mi++)
#pragma unroll
                for (int ni = 0; ni < 4; ni++) MMA16816(acc[mi][ni], al[mi], bh[ni]);
#pragma unroll
            for (int mi = 0; mi < 4; mi++)
#pragma unroll
                for (int ni = 0; ni < 4; ni++) MMA16816(acc[mi][ni], ah[mi], bl[ni]);
        }
    }

    // epilogue: direct fp32 writes + bias
    const int rbase = m0 + warp_m * 64 + (lane >> 2);
    const int cbase = n0 + warp_n * 32 + (lane & 3) * 2;
#pragma unroll
    for (int mi = 0; mi < 4; mi++) {
#pragma unroll
        for (int ni = 0; ni < 4; ni++) {
            int cc = cbase + ni * 8;
            float b0 = bias[cc], b1 = bias[cc + 1];
            int r0 = rbase + mi * 16;
            float2 w0 = make_float2(acc[mi][ni][0] + b0, acc[mi][ni][1] + b1);
            float2 w1 = make_float2(acc[mi][ni][2] + b0, acc[mi][ni][3] + b1);
            *(float2*)(C + (size_t)r0 * N + cc) = w0;
            *(float2*)(C + (size_t)(r0 + 8) * N + cc) = w1;
        }
    }
#undef LOAD_STAGE
}

// ---------------- fused window attention (fp32, reg-blocked) -----------------
// outputs pre-split halves for the proj GEMM
__global__ __launch_bounds__(256) void attn_kernel(
    const float* __restrict__ qkv, const float* __restrict__ comb,
    __half* __restrict__ outh, __half* __restrict__ outl)
{
    __shared__ __align__(16) float qs[SS][33];
    __shared__ __align__(16) float kst[HD][52];    // transposed K
    __shared__ __align__(16) float vs[SS][36];
    __shared__ __align__(16) float ps[SS][52];

    const int b = blockIdx.x, h = blockIdx.y, tid = threadIdx.x;
    const float scale = 0.17677669529663687f;  // 32^-0.5

    for (int i = tid; i < SS * HD; i += 256) {
        int s = i >> 5, d = i & 31;
        size_t row = (size_t)(b * SS + s) * QKV_N;
        qs[s][d]  = qkv[row + h * HD + d] * scale;
        kst[d][s] = qkv[row + DIMC + h * HD + d];
        vs[s][d]  = qkv[row + 2 * DIMC + h * HD + d];
    }
    __syncthreads();

    const int wg = b & (NWG - 1);
    const float* cb = comb + ((size_t)(wg * NHEADS + h)) * SS * 52;

    // logits: 2 rows x 4 cols per item
    for (int it = tid; it < 25 * 13; it += 256) {
        int rp = it / 13, jg = it - rp * 13;
        int i0 = rp * 2;
        int i1 = i0 + 1;
        int i1r = (i1 < SS) ? i1 : SS - 1;
        float4 a0 = make_float4(0.f, 0.f, 0.f, 0.f);
        float4 a1 = make_float4(0.f, 0.f, 0.f, 0.f);
#pragma unroll
        for (int d = 0; d < HD; d++) {
            float4 k4 = *(const float4*)&kst[d][jg * 4];
            float q0 = qs[i0][d], q1 = qs[i1r][d];
            a0.x += q0 * k4.x; a0.y += q0 * k4.y; a0.z += q0 * k4.z; a0.w += q0 * k4.w;
            a1.x += q1 * k4.x; a1.y += q1 * k4.y; a1.z += q1 * k4.z; a1.w += q1 * k4.w;
        }
        float4 c0 = *(const float4*)(cb + i0 * 52 + jg * 4);
        a0.x += c0.x; a0.y += c0.y; a0.z += c0.z; a0.w += c0.w;
        *(float4*)&ps[i0][jg * 4] = a0;
        if (i1 < SS) {
            float4 c1 = *(const float4*)(cb + i1 * 52 + jg * 4);
            a1.x += c1.x; a1.y += c1.y; a1.z += c1.z; a1.w += c1.w;
            *(float4*)&ps[i1][jg * 4] = a1;
        }
    }
    __syncthreads();

    // softmax: one warp per row
    const int wid = tid >> 5, lane = tid & 31;
    for (int i = wid; i < SS; i += 8) {
        float a0 = ps[i][lane];
        float a1 = (lane < SS - 32) ? ps[i][lane + 32] : -1e30f;
        float m = fmaxf(a0, a1);
#pragma unroll
        for (int off = 16; off > 0; off >>= 1)
            m = fmaxf(m, __shfl_xor_sync(0xffffffffu, m, off));
        float e0 = __expf(a0 - m);
        float e1 = (lane < SS - 32) ? __expf(a1 - m) : 0.f;
        float s = e0 + e1;
#pragma unroll
        for (int off = 16; off > 0; off >>= 1)
            s += __shfl_xor_sync(0xffffffffu, s, off);
        float inv = 1.f / s;
        ps[i][lane] = e0 * inv;
        if (lane < SS - 32) ps[i][lane + 32] = e1 * inv;
    }
    __syncthreads();

    // AV: 2 rows x 4 dims per item; write split halves
    for (int it = tid; it < 25 * 8; it += 256) {
        int rp = it >> 3, dg = it & 7;
        int i0 = rp * 2;
        int i1 = i0 + 1;
        int i1r = (i1 < SS) ? i1 : SS - 1;
        float4 a0 = make_float4(0.f, 0.f, 0.f, 0.f);
        float4 a1 = make_float4(0.f, 0.f, 0.f, 0.f);
#pragma unroll
        for (int j = 0; j < SS; j++) {
            float4 v4 = *(const float4*)&vs[j][dg * 4];
            float p0 = ps[i0][j], p1 = ps[i1r][j];
            a0.x += p0 * v4.x; a0.y += p0 * v4.y; a0.z += p0 * v4.z; a0.w += p0 * v4.w;
            a1.x += p1 * v4.x; a1.y += p1 * v4.y; a1.z += p1 * v4.z; a1.w += p1 * v4.w;
        }
#pragma unroll
        for (int rr = 0; rr < 2; rr++) {
            int i = i0 + rr;
            if (i >= SS) break;
            float4 a = rr ? a1 : a0;
            __half hx = __float2half_rn(a.x), hy = __float2half_rn(a.y);
            __half hz = __float2half_rn(a.z), hw = __float2half_rn(a.w);
            __half lx = __float2half_rn(a.x - __half2float(hx));
            __half ly = __float2half_rn(a.y - __half2float(hy));
            __half lz = __float2half_rn(a.z - __half2float(hz));
            __half lw = __float2half_rn(a.w - __half2float(hw));
            __half2 hp[2] = { __halves2half2(hx, hy), __halves2half2(hz, hw) };
            __half2 lp[2] = { __halves2half2(lx, ly), __halves2half2(lz, lw) };
            size_t off = (size_t)(b * SS + i) * DIMC + h * HD + dg * 4;
            *(uint2*)(outh + off) = *(uint2*)hp;
            *(uint2*)(outl + off) = *(uint2*)lp;
        }
    }
}

// ---------------- launch ------------------------------------------------------
extern "C" void kernel_launch(void* const* d_in, const int* in_sizes, int n_in,
                              void* d_out, int out_size)
{
    const float* x          = (const float*)d_in[0];
    const float* mask       = (const float*)d_in[1];
    const float* Wqkv       = (const float*)d_in[2];
    const float* bqkv       = (const float*)d_in[3];
    const float* Wproj      = (const float*)d_in[4];
    const float* bproj      = (const float*)d_in[5];
    const float* bias_table = (const float*)d_in[6];
    const int*   rel_index  = (const int*)d_in[7];
    float* out = (float*)d_out;

    float  *qkv, *comb;
    __half *xh, *xl, *wqh, *wql, *wph, *wpl;
    cudaGetSymbolAddress((void**)&qkv,  g_qkv);
    cudaGetSymbolAddress((void**)&comb, g_comb);
    cudaGetSymbolAddress((void**)&xh,   g_xh);
    cudaGetSymbolAddress((void**)&xl,   g_xl);
    cudaGetSymbolAddress((void**)&wqh,  g_wqh);
    cudaGetSymbolAddress((void**)&wql,  g_wql);
    cudaGetSymbolAddress((void**)&wph,  g_wph);
    cudaGetSymbolAddress((void**)&wpl,  g_wpl);

    cudaFuncSetAttribute(gemm_hmma, cudaFuncAttributeMaxDynamicSharedMemorySize, GEMM_SMEM);

    split_x<<<(size_t)TOKENS * KDIM / 1024, 256>>>(x, xh, xl);
    split_w<<<(KDIM * QKV_N + 255) / 256, 256>>>(Wqkv, wqh, wql, KDIM, QKV_N);
    split_w<<<(KDIM * DIMC  + 255) / 256, 256>>>(Wproj, wph, wpl, KDIM, DIMC);
    comb_k<<<(NWG * NHEADS * SS * 52 + 255) / 256, 256>>>(mask, bias_table, rel_index, comb);

    gemm_hmma<<<dim3(QKV_N / 128, TOKENS / 128), 256, GEMM_SMEM>>>(
        xh, xl, wqh, wql, bqkv, qkv, QKV_N);

    attn_kernel<<<dim3(4096, NHEADS), 256>>>(qkv, comb, xh, xl);

    gemm_hmma<<<dim3(DIMC / 128, TOKENS / 128), 256, GEMM_SMEM>>>(
        xh, xl, wph, wpl, bproj, out, DIMC);
}

// round 8
// speedup vs baseline: 4.7044x; 1.2400x over previous
#include <cuda_runtime.h>
#include <cuda_fp16.h>
#include <cstdint>

#define TOKENS   200704      // 4096 * 49
#define DIMC     512
#define QKV_N    1536
#define KDIM     512
#define SS       49
#define NHEADS   16
#define HD       32
#define NWG      64

// ---------------- scratch ---------------------------------------------------
__device__ float  g_qkv[(size_t)TOKENS * QKV_N];     // 1.23 GB
__device__ __half g_xh[(size_t)TOKENS * KDIM];       // split A (reused for attn out)
__device__ __half g_xl[(size_t)TOKENS * KDIM];
__device__ __half g_wqh[(size_t)QKV_N * KDIM];       // Wqkv^T fp16
__device__ __half g_wph[(size_t)DIMC * KDIM];        // Wproj^T fp16
__device__ float  g_comb[(size_t)NWG * NHEADS * SS * 52];  // bias+mask, padded rows

// ---------------- asm helpers -----------------------------------------------
__device__ __forceinline__ uint32_t smem_u32(const void* p) {
    uint32_t a;
    asm("{ .reg .u64 t; cvta.to.shared.u64 t, %1; cvt.u32.u64 %0, t; }" : "=r"(a) : "l"(p));
    return a;
}

#define CP16(d, s) asm volatile("cp.async.cg.shared.global [%0], [%1], 16;" :: "r"(d), "l"(s))
#define CP_COMMIT() asm volatile("cp.async.commit_group;" ::: "memory")
#define CP_WAIT1()  asm volatile("cp.async.wait_group 1;" ::: "memory")
#define CP_WAIT0()  asm volatile("cp.async.wait_group 0;" ::: "memory")

#define LDSM4(R, a) asm volatile( \
    "ldmatrix.sync.aligned.m8n8.x4.shared.b16 {%0,%1,%2,%3}, [%4];" \
    : "=r"((R)[0]),"=r"((R)[1]),"=r"((R)[2]),"=r"((R)[3]) : "r"(a))
#define LDSM2(R, a) asm volatile( \
    "ldmatrix.sync.aligned.m8n8.x2.shared.b16 {%0,%1}, [%2];" \
    : "=r"((R)[0]),"=r"((R)[1]) : "r"(a))

#define MMA16816(Cc, Aa, Bb) asm volatile( \
    "mma.sync.aligned.m16n8k16.row.col.f32.f16.f16.f32 " \
    "{%0,%1,%2,%3}, {%4,%5,%6,%7}, {%8,%9}, {%0,%1,%2,%3};" \
    : "+f"((Cc)[0]),"+f"((Cc)[1]),"+f"((Cc)[2]),"+f"((Cc)[3]) \
    : "r"((Aa)[0]),"r"((Aa)[1]),"r"((Aa)[2]),"r"((Aa)[3]), "r"((Bb)[0]),"r"((Bb)[1]))

// ---------------- split / convert kernels -------------------------------------
__global__ __launch_bounds__(256) void split_x(const float* __restrict__ in,
                                               __half* __restrict__ oh,
                                               __half* __restrict__ ol)
{
    size_t base = ((size_t)blockIdx.x * 256 + threadIdx.x) * 4;
    float4 f = *(const float4*)(in + base);
    __half hx = __float2half_rn(f.x), hy = __float2half_rn(f.y);
    __half hz = __float2half_rn(f.z), hw = __float2half_rn(f.w);
    __half lx = __float2half_rn(f.x - __half2float(hx));
    __half ly = __float2half_rn(f.y - __half2float(hy));
    __half lz = __float2half_rn(f.z - __half2float(hz));
    __half lw = __float2half_rn(f.w - __half2float(hw));
    __half2 h2[2] = { __halves2half2(hx, hy), __halves2half2(hz, hw) };
    __half2 l2[2] = { __halves2half2(lx, ly), __halves2half2(lz, lw) };
    *(uint2*)(oh + base) = *(uint2*)h2;
    *(uint2*)(ol + base) = *(uint2*)l2;
}

__global__ __launch_bounds__(256) void conv_w(const float* __restrict__ in,
                                              __half* __restrict__ oh, int K, int N)
{
    int t = blockIdx.x * 256 + threadIdx.x;
    if (t >= K * N) return;
    int k = t / N, n = t - k * N;
    oh[(size_t)n * K + k] = __float2half_rn(in[t]);   // W^T layout [n][k]
}

// ---------------- comb = bias-gather + mask (padded rows of 52) --------------
__global__ __launch_bounds__(256) void comb_k(const float* __restrict__ mask,
                                              const float* __restrict__ bias_table,
                                              const int* __restrict__ rel_index,
                                              float* __restrict__ comb)
{
    int idx = blockIdx.x * 256 + threadIdx.x;
    const int total = NWG * NHEADS * SS * 52;
    if (idx >= total) return;
    int j = idx % 52;
    int t = idx / 52;
    int i = t % SS;  t /= SS;
    int h = t % NHEADS;
    int g = t / NHEADS;
    float v = 0.f;
    if (j < SS)
        v = bias_table[rel_index[i * SS + j] * NHEADS + h] + mask[((size_t)g * SS + i) * SS + j];
    comb[idx] = v;
}

// ---------------- HMMA 2-product GEMM -----------------------------------------
// C[M,N] = (Ah+Al)[M,512] @ Bh[N,512]^T + bias   (A exact via split, W fp16)
// Block 128x128, BK=64, 3-stage cp.async, warp tile 64x32 (2x4 warp grid).
#define STAGE_BYTES 49152
#define GEMM_SMEM   (3 * STAGE_BYTES)

__global__ __launch_bounds__(256) void gemm_hmma(
    const __half* __restrict__ Ahp, const __half* __restrict__ Alp,
    const __half* __restrict__ Bhp,
    const float* __restrict__ bias, float* __restrict__ C, int N)
{
    extern __shared__ char smem[];
    const uint32_t sb = smem_u32(smem);
    const int tid = threadIdx.x, wid = tid >> 5, lane = tid & 31;
    const int m0 = blockIdx.y * 128, n0 = blockIdx.x * 128;
    const int warp_m = wid & 1, warp_n = wid >> 1;

    float acc[4][4][4];
#pragma unroll
    for (int a = 0; a < 4; a++)
#pragma unroll
        for (int b = 0; b < 4; b++)
#pragma unroll
            for (int c = 0; c < 4; c++) acc[a][b][c] = 0.f;

    // per-lane cp.async coords
    const int cr0 = tid >> 3;        // row for u=0 (increments by 32 per u)
    const int ckc = tid & 7;         // 16B chunk within 128B row

#define LOAD_STAGE(st, ch) do {                                              \
        uint32_t sp_ = sb + (st) * STAGE_BYTES;                              \
        int kt_ = (ch) * 64;                                                 \
        _Pragma("unroll")                                                    \
        for (int u = 0; u < 4; u++) {                                        \
            int r_ = cr0 + u * 32;                                           \
            uint32_t d_ = sp_ + r_ * 128 + (((uint32_t)(ckc ^ (r_ & 7))) << 4); \
            size_t so_ = (size_t)kt_ + ckc * 8;                              \
            CP16(d_,         Ahp + (size_t)(m0 + r_) * KDIM + so_);          \
            CP16(d_ + 16384, Alp + (size_t)(m0 + r_) * KDIM + so_);          \
            CP16(d_ + 32768, Bhp + (size_t)(n0 + r_) * KDIM + so_);          \
        }                                                                    \
    } while (0)

    LOAD_STAGE(0, 0); CP_COMMIT();
    LOAD_STAGE(1, 1); CP_COMMIT();

    // ldmatrix lane geometry
    const int g  = lane >> 3;          // 0..3 (A x4 groups)
    const int lr = lane & 7;
    const int gh = g >> 1;             // A k-half select
    const int lrB = lane & 7, hB = (lane >> 3) & 1;
    const uint32_t aRow = (uint32_t)((warp_m * 64 + (g & 1) * 8 + lr) * 128);
    const uint32_t bRow = (uint32_t)((warp_n * 32 + lrB) * 128);

    for (int c = 0; c < 8; c++) {
        if (c < 7) CP_WAIT1(); else CP_WAIT0();
        __syncthreads();
        if (c + 2 < 8) { LOAD_STAGE((c + 2) % 3, c + 2); CP_COMMIT(); }

        const uint32_t As = sb + (c % 3) * STAGE_BYTES;
        const uint32_t Bs = As + 32768;
#pragma unroll
        for (int ks = 0; ks < 4; ks++) {
            uint32_t ah[4][4], al[4][4], bh[4][2];
            const uint32_t cA = (uint32_t)(((ks * 2 + gh) ^ lr) << 4);
            const uint32_t cB = (uint32_t)(((ks * 2 + hB) ^ lrB) << 4);
#pragma unroll
            for (int mi = 0; mi < 4; mi++) LDSM4(ah[mi], As + aRow + mi * 2048 + cA);
#pragma unroll
            for (int ni = 0; ni < 4; ni++) LDSM2(bh[ni], Bs + bRow + ni * 1024 + cB);
#pragma unroll
            for (int mi = 0; mi < 4; mi++)
#pragma unroll
                for (int ni = 0; ni < 4; ni++) MMA16816(acc[mi][ni], ah[mi], bh[ni]);
#pragma unroll
            for (int mi = 0; mi < 4; mi++) LDSM4(al[mi], As + 16384 + aRow + mi * 2048 + cA);
#pragma unroll
            for (int mi = 0; mi < 4; mi++)
#pragma unroll
                for (int ni = 0; ni < 4; ni++) MMA16816(acc[mi][ni], al[mi], bh[ni]);
        }
    }

    // epilogue: direct fp32 writes + bias
    const int rbase = m0 + warp_m * 64 + (lane >> 2);
    const int cbase = n0 + warp_n * 32 + (lane & 3) * 2;
#pragma unroll
    for (int mi = 0; mi < 4; mi++) {
#pragma unroll
        for (int ni = 0; ni < 4; ni++) {
            int cc = cbase + ni * 8;
            float b0 = bias[cc], b1 = bias[cc + 1];
            int r0 = rbase + mi * 16;
            float2 w0 = make_float2(acc[mi][ni][0] + b0, acc[mi][ni][1] + b1);
            float2 w1 = make_float2(acc[mi][ni][2] + b0, acc[mi][ni][3] + b1);
            *(float2*)(C + (size_t)r0 * N + cc) = w0;
            *(float2*)(C + (size_t)(r0 + 8) * N + cc) = w1;
        }
    }
#undef LOAD_STAGE
}

// ---------------- fused window attention (fp32, reg-blocked) -----------------
// outputs pre-split halves for the proj GEMM
__global__ __launch_bounds__(256) void attn_kernel(
    const float* __restrict__ qkv, const float* __restrict__ comb,
    __half* __restrict__ outh, __half* __restrict__ outl)
{
    __shared__ __align__(16) float qs[SS][33];
    __shared__ __align__(16) float kst[HD][52];    // transposed K
    __shared__ __align__(16) float vs[SS][36];
    __shared__ __align__(16) float ps[SS][52];

    const int b = blockIdx.x, h = blockIdx.y, tid = threadIdx.x;
    const float scale = 0.17677669529663687f;  // 32^-0.5

    for (int i = tid; i < SS * HD; i += 256) {
        int s = i >> 5, d = i & 31;
        size_t row = (size_t)(b * SS + s) * QKV_N;
        qs[s][d]  = qkv[row + h * HD + d] * scale;
        kst[d][s] = qkv[row + DIMC + h * HD + d];
        vs[s][d]  = qkv[row + 2 * DIMC + h * HD + d];
    }
    __syncthreads();

    const int wg = b & (NWG - 1);
    const float* cb = comb + ((size_t)(wg * NHEADS + h)) * SS * 52;

    // logits: 2 rows x 4 cols per item
    for (int it = tid; it < 25 * 13; it += 256) {
        int rp = it / 13, jg = it - rp * 13;
        int i0 = rp * 2;
        int i1 = i0 + 1;
        int i1r = (i1 < SS) ? i1 : SS - 1;
        float4 a0 = make_float4(0.f, 0.f, 0.f, 0.f);
        float4 a1 = make_float4(0.f, 0.f, 0.f, 0.f);
#pragma unroll
        for (int d = 0; d < HD; d++) {
            float4 k4 = *(const float4*)&kst[d][jg * 4];
            float q0 = qs[i0][d], q1 = qs[i1r][d];
            a0.x += q0 * k4.x; a0.y += q0 * k4.y; a0.z += q0 * k4.z; a0.w += q0 * k4.w;
            a1.x += q1 * k4.x; a1.y += q1 * k4.y; a1.z += q1 * k4.z; a1.w += q1 * k4.w;
        }
        float4 c0 = *(const float4*)(cb + i0 * 52 + jg * 4);
        a0.x += c0.x; a0.y += c0.y; a0.z += c0.z; a0.w += c0.w;
        *(float4*)&ps[i0][jg * 4] = a0;
        if (i1 < SS) {
            float4 c1 = *(const float4*)(cb + i1 * 52 + jg * 4);
            a1.x += c1.x; a1.y += c1.y; a1.z += c1.z; a1.w += c1.w;
            *(float4*)&ps[i1][jg * 4] = a1;
        }
    }
    __syncthreads();

    // softmax: one warp per row
    const int wid = tid >> 5, lane = tid & 31;
    for (int i = wid; i < SS; i += 8) {
        float a0 = ps[i][lane];
        float a1 = (lane < SS - 32) ? ps[i][lane + 32] : -1e30f;
        float m = fmaxf(a0, a1);
#pragma unroll
        for (int off = 16; off > 0; off >>= 1)
            m = fmaxf(m, __shfl_xor_sync(0xffffffffu, m, off));
        float e0 = __expf(a0 - m);
        float e1 = (lane < SS - 32) ? __expf(a1 - m) : 0.f;
        float s = e0 + e1;
#pragma unroll
        for (int off = 16; off > 0; off >>= 1)
            s += __shfl_xor_sync(0xffffffffu, s, off);
        float inv = 1.f / s;
        ps[i][lane] = e0 * inv;
        if (lane < SS - 32) ps[i][lane + 32] = e1 * inv;
    }
    __syncthreads();

    // AV: 2 rows x 4 dims per item; write split halves
    for (int it = tid; it < 25 * 8; it += 256) {
        int rp = it >> 3, dg = it & 7;
        int i0 = rp * 2;
        int i1 = i0 + 1;
        int i1r = (i1 < SS) ? i1 : SS - 1;
        float4 a0 = make_float4(0.f, 0.f, 0.f, 0.f);
        float4 a1 = make_float4(0.f, 0.f, 0.f, 0.f);
#pragma unroll
        for (int j = 0; j < SS; j++) {
            float4 v4 = *(const float4*)&vs[j][dg * 4];
            float p0 = ps[i0][j], p1 = ps[i1r][j];
            a0.x += p0 * v4.x; a0.y += p0 * v4.y; a0.z += p0 * v4.z; a0.w += p0 * v4.w;
            a1.x += p1 * v4.x; a1.y += p1 * v4.y; a1.z += p1 * v4.z; a1.w += p1 * v4.w;
        }
#pragma unroll
        for (int rr = 0; rr < 2; rr++) {
            int i = i0 + rr;
            if (i >= SS) break;
            float4 a = rr ? a1 : a0;
            __half hx = __float2half_rn(a.x), hy = __float2half_rn(a.y);
            __half hz = __float2half_rn(a.z), hw = __float2half_rn(a.w);
            __half lx = __float2half_rn(a.x - __half2float(hx));
            __half ly = __float2half_rn(a.y - __half2float(hy));
            __half lz = __float2half_rn(a.z - __half2float(hz));
            __half lw = __float2half_rn(a.w - __half2float(hw));
            __half2 hp[2] = { __halves2half2(hx, hy), __halves2half2(hz, hw) };
            __half2 lp[2] = { __halves2half2(lx, ly), __halves2half2(lz, lw) };
            size_t off = (size_t)(b * SS + i) * DIMC + h * HD + dg * 4;
            *(uint2*)(outh + off) = *(uint2*)hp;
            *(uint2*)(outl + off) = *(uint2*)lp;
        }
    }
}

// ---------------- launch ------------------------------------------------------
extern "C" void kernel_launch(void* const* d_in, const int* in_sizes, int n_in,
                              void* d_out, int out_size)
{
    const float* x          = (const float*)d_in[0];
    const float* mask       = (const float*)d_in[1];
    const float* Wqkv       = (const float*)d_in[2];
    const float* bqkv       = (const float*)d_in[3];
    const float* Wproj      = (const float*)d_in[4];
    const float* bproj      = (const float*)d_in[5];
    const float* bias_table = (const float*)d_in[6];
    const int*   rel_index  = (const int*)d_in[7];
    float* out = (float*)d_out;

    float  *qkv, *comb;
    __half *xh, *xl, *wqh, *wph;
    cudaGetSymbolAddress((void**)&qkv,  g_qkv);
    cudaGetSymbolAddress((void**)&comb, g_comb);
    cudaGetSymbolAddress((void**)&xh,   g_xh);
    cudaGetSymbolAddress((void**)&xl,   g_xl);
    cudaGetSymbolAddress((void**)&wqh,  g_wqh);
    cudaGetSymbolAddress((void**)&wph,  g_wph);

    cudaFuncSetAttribute(gemm_hmma, cudaFuncAttributeMaxDynamicSharedMemorySize, GEMM_SMEM);

    split_x<<<(size_t)TOKENS * KDIM / 1024, 256>>>(x, xh, xl);
    conv_w<<<(KDIM * QKV_N + 255) / 256, 256>>>(Wqkv, wqh, KDIM, QKV_N);
    conv_w<<<(KDIM * DIMC  + 255) / 256, 256>>>(Wproj, wph, KDIM, DIMC);
    comb_k<<<(NWG * NHEADS * SS * 52 + 255) / 256, 256>>>(mask, bias_table, rel_index, comb);

    gemm_hmma<<<dim3(QKV_N / 128, TOKENS / 128), 256, GEMM_SMEM>>>(
        xh, xl, wqh, bqkv, qkv, QKV_N);

    attn_kernel<<<dim3(4096, NHEADS), 256>>>(qkv, comb, xh, xl);

    gemm_hmma<<<dim3(DIMC / 128, TOKENS / 128), 256, GEMM_SMEM>>>(
        xh, xl, wph, bproj, out, DIMC);
}

// round 9
// speedup vs baseline: 6.5897x; 1.4007x over previous
#include <cuda_runtime.h>
#include <cuda_fp16.h>
#include <cstdint>

#define TOKENS   200704      // 4096 * 49
#define DIMC     512
#define QKV_N    1536
#define KDIM     512
#define SS       49
#define NHEADS   16
#define HD       32
#define NWG      64

// ---------------- scratch ---------------------------------------------------
__device__ float  g_qkv[(size_t)TOKENS * QKV_N];     // 1.23 GB
__device__ __half g_xh[(size_t)TOKENS * KDIM];       // fp16 activations (reused for attn out)
__device__ __half g_wqh[(size_t)QKV_N * KDIM];       // Wqkv^T fp16
__device__ __half g_wph[(size_t)DIMC * KDIM];        // Wproj^T fp16
__device__ float  g_comb[(size_t)NWG * NHEADS * SS * 52];  // bias+mask, padded rows

// ---------------- asm helpers -----------------------------------------------
__device__ __forceinline__ uint32_t smem_u32(const void* p) {
    uint32_t a;
    asm("{ .reg .u64 t; cvta.to.shared.u64 t, %1; cvt.u32.u64 %0, t; }" : "=r"(a) : "l"(p));
    return a;
}

#define CP16(d, s) asm volatile("cp.async.cg.shared.global [%0], [%1], 16;" :: "r"(d), "l"(s))
#define CP_COMMIT() asm volatile("cp.async.commit_group;" ::: "memory")
#define CP_WAIT1()  asm volatile("cp.async.wait_group 1;" ::: "memory")
#define CP_WAIT0()  asm volatile("cp.async.wait_group 0;" ::: "memory")

#define LDSM4(R, a) asm volatile( \
    "ldmatrix.sync.aligned.m8n8.x4.shared.b16 {%0,%1,%2,%3}, [%4];" \
    : "=r"((R)[0]),"=r"((R)[1]),"=r"((R)[2]),"=r"((R)[3]) : "r"(a))
#define LDSM2(R, a) asm volatile( \
    "ldmatrix.sync.aligned.m8n8.x2.shared.b16 {%0,%1}, [%2];" \
    : "=r"((R)[0]),"=r"((R)[1]) : "r"(a))

#define MMA16816(Cc, Aa, Bb) asm volatile( \
    "mma.sync.aligned.m16n8k16.row.col.f32.f16.f16.f32 " \
    "{%0,%1,%2,%3}, {%4,%5,%6,%7}, {%8,%9}, {%0,%1,%2,%3};" \
    : "+f"((Cc)[0]),"+f"((Cc)[1]),"+f"((Cc)[2]),"+f"((Cc)[3]) \
    : "r"((Aa)[0]),"r"((Aa)[1]),"r"((Aa)[2]),"r"((Aa)[3]), "r"((Bb)[0]),"r"((Bb)[1]))

// ---------------- convert kernels --------------------------------------------
__global__ __launch_bounds__(256) void conv_x(const float* __restrict__ in,
                                              __half* __restrict__ oh)
{
    size_t base = ((size_t)blockIdx.x * 256 + threadIdx.x) * 4;
    float4 f = *(const float4*)(in + base);
    __half2 h2[2] = { __halves2half2(__float2half_rn(f.x), __float2half_rn(f.y)),
                      __halves2half2(__float2half_rn(f.z), __float2half_rn(f.w)) };
    *(uint2*)(oh + base) = *(uint2*)h2;
}

__global__ __launch_bounds__(256) void conv_w(const float* __restrict__ in,
                                              __half* __restrict__ oh, int K, int N)
{
    int t = blockIdx.x * 256 + threadIdx.x;
    if (t >= K * N) return;
    int k = t / N, n = t - k * N;
    oh[(size_t)n * K + k] = __float2half_rn(in[t]);   // W^T layout [n][k]
}

// ---------------- comb = bias-gather + mask (padded rows of 52) --------------
__global__ __launch_bounds__(256) void comb_k(const float* __restrict__ mask,
                                              const float* __restrict__ bias_table,
                                              const int* __restrict__ rel_index,
                                              float* __restrict__ comb)
{
    int idx = blockIdx.x * 256 + threadIdx.x;
    const int total = NWG * NHEADS * SS * 52;
    if (idx >= total) return;
    int j = idx % 52;
    int t = idx / 52;
    int i = t % SS;  t /= SS;
    int h = t % NHEADS;
    int g = t / NHEADS;
    float v = 0.f;
    if (j < SS)
        v = bias_table[rel_index[i * SS + j] * NHEADS + h] + mask[((size_t)g * SS + i) * SS + j];
    comb[idx] = v;
}

// ---------------- HMMA fp16 GEMM ----------------------------------------------
// C[M,N] = A[M,512] @ B[N,512]^T + bias   (both fp16, fp32 accum)
// Block 128x128, BK=64, 3-stage cp.async, warp tile 64x32 (2x4 warp grid).
#define STAGE_BYTES 32768
#define GEMM_SMEM   (3 * STAGE_BYTES)

__global__ __launch_bounds__(256) void gemm_hmma(
    const __half* __restrict__ Ahp, const __half* __restrict__ Bhp,
    const float* __restrict__ bias, float* __restrict__ C, int N)
{
    extern __shared__ char smem[];
    const uint32_t sb = smem_u32(smem);
    const int tid = threadIdx.x, wid = tid >> 5, lane = tid & 31;
    const int m0 = blockIdx.y * 128, n0 = blockIdx.x * 128;
    const int warp_m = wid & 1, warp_n = wid >> 1;

    float acc[4][4][4];
#pragma unroll
    for (int a = 0; a < 4; a++)
#pragma unroll
        for (int b = 0; b < 4; b++)
#pragma unroll
            for (int c = 0; c < 4; c++) acc[a][b][c] = 0.f;

    // per-lane cp.async coords
    const int cr0 = tid >> 3;        // row for u=0 (increments by 32 per u)
    const int ckc = tid & 7;         // 16B chunk within 128B row

#define LOAD_STAGE(st, ch) do {                                              \
        uint32_t sp_ = sb + (st) * STAGE_BYTES;                              \
        int kt_ = (ch) * 64;                                                 \
        _Pragma("unroll")                                                    \
        for (int u = 0; u < 4; u++) {                                        \
            int r_ = cr0 + u * 32;                                           \
            uint32_t d_ = sp_ + r_ * 128 + (((uint32_t)(ckc ^ (r_ & 7))) << 4); \
            size_t so_ = (size_t)kt_ + ckc * 8;                              \
            CP16(d_,         Ahp + (size_t)(m0 + r_) * KDIM + so_);          \
            CP16(d_ + 16384, Bhp + (size_t)(n0 + r_) * KDIM + so_);          \
        }                                                                    \
    } while (0)

    LOAD_STAGE(0, 0); CP_COMMIT();
    LOAD_STAGE(1, 1); CP_COMMIT();

    // ldmatrix lane geometry
    const int g  = lane >> 3;          // 0..3 (A x4 groups)
    const int lr = lane & 7;
    const int gh = g >> 1;             // A k-half select
    const int lrB = lane & 7, hB = (lane >> 3) & 1;
    const uint32_t aRow = (uint32_t)((warp_m * 64 + (g & 1) * 8 + lr) * 128);
    const uint32_t bRow = (uint32_t)((warp_n * 32 + lrB) * 128);

    for (int c = 0; c < 8; c++) {
        if (c < 7) CP_WAIT1(); else CP_WAIT0();
        __syncthreads();
        if (c + 2 < 8) { LOAD_STAGE((c + 2) % 3, c + 2); CP_COMMIT(); }

        const uint32_t As = sb + (c % 3) * STAGE_BYTES;
        const uint32_t Bs = As + 16384;
#pragma unroll
        for (int ks = 0; ks < 4; ks++) {
            uint32_t ah[4][4], bh[4][2];
            const uint32_t cA = (uint32_t)(((ks * 2 + gh) ^ lr) << 4);
            const uint32_t cB = (uint32_t)(((ks * 2 + hB) ^ lrB) << 4);
#pragma unroll
            for (int mi = 0; mi < 4; mi++) LDSM4(ah[mi], As + aRow + mi * 2048 + cA);
#pragma unroll
            for (int ni = 0; ni < 4; ni++) LDSM2(bh[ni], Bs + bRow + ni * 1024 + cB);
#pragma unroll
            for (int mi = 0; mi < 4; mi++)
#pragma unroll
                for (int ni = 0; ni < 4; ni++) MMA16816(acc[mi][ni], ah[mi], bh[ni]);
        }
    }

    // epilogue: direct fp32 writes + bias
    const int rbase = m0 + warp_m * 64 + (lane >> 2);
    const int cbase = n0 + warp_n * 32 + (lane & 3) * 2;
#pragma unroll
    for (int mi = 0; mi < 4; mi++) {
#pragma unroll
        for (int ni = 0; ni < 4; ni++) {
            int cc = cbase + ni * 8;
            float b0 = bias[cc], b1 = bias[cc + 1];
            int r0 = rbase + mi * 16;
            float2 w0 = make_float2(acc[mi][ni][0] + b0, acc[mi][ni][1] + b1);
            float2 w1 = make_float2(acc[mi][ni][2] + b0, acc[mi][ni][3] + b1);
            *(float2*)(C + (size_t)r0 * N + cc) = w0;
            *(float2*)(C + (size_t)(r0 + 8) * N + cc) = w1;
        }
    }
#undef LOAD_STAGE
}

// ---------------- fused window attention (fp32, reg-blocked) -----------------
// outputs fp16 activations for the proj GEMM
__global__ __launch_bounds__(256) void attn_kernel(
    const float* __restrict__ qkv, const float* __restrict__ comb,
    __half* __restrict__ outh)
{
    __shared__ __align__(16) float qs[SS][33];
    __shared__ __align__(16) float kst[HD][52];    // transposed K
    __shared__ __align__(16) float vs[SS][36];
    __shared__ __align__(16) float ps[SS][52];

    const int b = blockIdx.x, h = blockIdx.y, tid = threadIdx.x;
    const float scale = 0.17677669529663687f;  // 32^-0.5

    for (int i = tid; i < SS * HD; i += 256) {
        int s = i >> 5, d = i & 31;
        size_t row = (size_t)(b * SS + s) * QKV_N;
        qs[s][d]  = qkv[row + h * HD + d] * scale;
        kst[d][s] = qkv[row + DIMC + h * HD + d];
        vs[s][d]  = qkv[row + 2 * DIMC + h * HD + d];
    }
    __syncthreads();

    const int wg = b & (NWG - 1);
    const float* cb = comb + ((size_t)(wg * NHEADS + h)) * SS * 52;

    // logits: 2 rows x 4 cols per item
    for (int it = tid; it < 25 * 13; it += 256) {
        int rp = it / 13, jg = it - rp * 13;
        int i0 = rp * 2;
        int i1 = i0 + 1;
        int i1r = (i1 < SS) ? i1 : SS - 1;
        float4 a0 = make_float4(0.f, 0.f, 0.f, 0.f);
        float4 a1 = make_float4(0.f, 0.f, 0.f, 0.f);
#pragma unroll
        for (int d = 0; d < HD; d++) {
            float4 k4 = *(const float4*)&kst[d][jg * 4];
            float q0 = qs[i0][d], q1 = qs[i1r][d];
            a0.x += q0 * k4.x; a0.y += q0 * k4.y; a0.z += q0 * k4.z; a0.w += q0 * k4.w;
            a1.x += q1 * k4.x; a1.y += q1 * k4.y; a1.z += q1 * k4.z; a1.w += q1 * k4.w;
        }
        float4 c0 = *(const float4*)(cb + i0 * 52 + jg * 4);
        a0.x += c0.x; a0.y += c0.y; a0.z += c0.z; a0.w += c0.w;
        *(float4*)&ps[i0][jg * 4] = a0;
        if (i1 < SS) {
            float4 c1 = *(const float4*)(cb + i1 * 52 + jg * 4);
            a1.x += c1.x; a1.y += c1.y; a1.z += c1.z; a1.w += c1.w;
            *(float4*)&ps[i1][jg * 4] = a1;
        }
    }
    __syncthreads();

    // softmax: one warp per row
    const int wid = tid >> 5, lane = tid & 31;
    for (int i = wid; i < SS; i += 8) {
        float a0 = ps[i][lane];
        float a1 = (lane < SS - 32) ? ps[i][lane + 32] : -1e30f;
        float m = fmaxf(a0, a1);
#pragma unroll
        for (int off = 16; off > 0; off >>= 1)
            m = fmaxf(m, __shfl_xor_sync(0xffffffffu, m, off));
        float e0 = __expf(a0 - m);
        float e1 = (lane < SS - 32) ? __expf(a1 - m) : 0.f;
        float s = e0 + e1;
#pragma unroll
        for (int off = 16; off > 0; off >>= 1)
            s += __shfl_xor_sync(0xffffffffu, s, off);
        float inv = 1.f / s;
        ps[i][lane] = e0 * inv;
        if (lane < SS - 32) ps[i][lane + 32] = e1 * inv;
    }
    __syncthreads();

    // AV: 2 rows x 4 dims per item; write fp16
    for (int it = tid; it < 25 * 8; it += 256) {
        int rp = it >> 3, dg = it & 7;
        int i0 = rp * 2;
        int i1 = i0 + 1;
        int i1r = (i1 < SS) ? i1 : SS - 1;
        float4 a0 = make_float4(0.f, 0.f, 0.f, 0.f);
        float4 a1 = make_float4(0.f, 0.f, 0.f, 0.f);
#pragma unroll
        for (int j = 0; j < SS; j++) {
            float4 v4 = *(const float4*)&vs[j][dg * 4];
            float p0 = ps[i0][j], p1 = ps[i1r][j];
            a0.x += p0 * v4.x; a0.y += p0 * v4.y; a0.z += p0 * v4.z; a0.w += p0 * v4.w;
            a1.x += p1 * v4.x; a1.y += p1 * v4.y; a1.z += p1 * v4.z; a1.w += p1 * v4.w;
        }
#pragma unroll
        for (int rr = 0; rr < 2; rr++) {
            int i = i0 + rr;
            if (i >= SS) break;
            float4 a = rr ? a1 : a0;
            __half2 hp[2] = { __halves2half2(__float2half_rn(a.x), __float2half_rn(a.y)),
                              __halves2half2(__float2half_rn(a.z), __float2half_rn(a.w)) };
            size_t off = (size_t)(b * SS + i) * DIMC + h * HD + dg * 4;
            *(uint2*)(outh + off) = *(uint2*)hp;
        }
    }
}

// ---------------- launch ------------------------------------------------------
extern "C" void kernel_launch(void* const* d_in, const int* in_sizes, int n_in,
                              void* d_out, int out_size)
{
    const float* x          = (const float*)d_in[0];
    const float* mask       = (const float*)d_in[1];
    const float* Wqkv       = (const float*)d_in[2];
    const float* bqkv       = (const float*)d_in[3];
    const float* Wproj      = (const float*)d_in[4];
    const float* bproj      = (const float*)d_in[5];
    const float* bias_table = (const float*)d_in[6];
    const int*   rel_index  = (const int*)d_in[7];
    float* out = (float*)d_out;

    float  *qkv, *comb;
    __half *xh, *wqh, *wph;
    cudaGetSymbolAddress((void**)&qkv,  g_qkv);
    cudaGetSymbolAddress((void**)&comb, g_comb);
    cudaGetSymbolAddress((void**)&xh,   g_xh);
    cudaGetSymbolAddress((void**)&wqh,  g_wqh);
    cudaGetSymbolAddress((void**)&wph,  g_wph);

    cudaFuncSetAttribute(gemm_hmma, cudaFuncAttributeMaxDynamicSharedMemorySize, GEMM_SMEM);

    conv_x<<<(size_t)TOKENS * KDIM / 1024, 256>>>(x, xh);
    conv_w<<<(KDIM * QKV_N + 255) / 256, 256>>>(Wqkv, wqh, KDIM, QKV_N);
    conv_w<<<(KDIM * DIMC  + 255) / 256, 256>>>(Wproj, wph, KDIM, DIMC);
    comb_k<<<(NWG * NHEADS * SS * 52 + 255) / 256, 256>>>(mask, bias_table, rel_index, comb);

    gemm_hmma<<<dim3(QKV_N / 128, TOKENS / 128), 256, GEMM_SMEM>>>(
        xh, wqh, bqkv, qkv, QKV_N);

    attn_kernel<<<dim3(4096, NHEADS), 256>>>(qkv, comb, xh);

    gemm_hmma<<<dim3(DIMC / 128, TOKENS / 128), 256, GEMM_SMEM>>>(
        xh, wph, bproj, out, DIMC);
}

// round 10
// speedup vs baseline: 8.9412x; 1.3568x over previous
#include <cuda_runtime.h>
#include <cuda_fp16.h>
#include <cstdint>

#define TOKENS   200704      // 4096 * 49
#define DIMC     512
#define QKV_N    1536
#define KDIM     512
#define SS       49
#define NHEADS   16
#define HD       32
#define NWG      64

// ---------------- scratch ---------------------------------------------------
__device__ __half g_qkvh[(size_t)TOKENS * QKV_N];    // 617 MB fp16 qkv
__device__ __half g_xh[(size_t)TOKENS * KDIM];       // fp16 activations (reused for attn out)
__device__ __half g_wqh[(size_t)QKV_N * KDIM];       // Wqkv^T fp16
__device__ __half g_wph[(size_t)DIMC * KDIM];        // Wproj^T fp16
__device__ __half g_comb2[(size_t)NWG * NHEADS * 64 * 56];  // bias+mask fp16, padded

// ---------------- asm helpers -----------------------------------------------
__device__ __forceinline__ uint32_t smem_u32(const void* p) {
    uint32_t a;
    asm("{ .reg .u64 t; cvta.to.shared.u64 t, %1; cvt.u32.u64 %0, t; }" : "=r"(a) : "l"(p));
    return a;
}

#define CP16(d, s) asm volatile("cp.async.cg.shared.global [%0], [%1], 16;" :: "r"(d), "l"(s))
#define CP_COMMIT() asm volatile("cp.async.commit_group;" ::: "memory")
#define CP_WAIT1()  asm volatile("cp.async.wait_group 1;" ::: "memory")
#define CP_WAIT0()  asm volatile("cp.async.wait_group 0;" ::: "memory")

#define LDSM4(R, a) asm volatile( \
    "ldmatrix.sync.aligned.m8n8.x4.shared.b16 {%0,%1,%2,%3}, [%4];" \
    : "=r"((R)[0]),"=r"((R)[1]),"=r"((R)[2]),"=r"((R)[3]) : "r"(a))
#define LDSM2(R, a) asm volatile( \
    "ldmatrix.sync.aligned.m8n8.x2.shared.b16 {%0,%1}, [%2];" \
    : "=r"((R)[0]),"=r"((R)[1]) : "r"(a))

#define MMA16816(Cc, Aa, Bb) asm volatile( \
    "mma.sync.aligned.m16n8k16.row.col.f32.f16.f16.f32 " \
    "{%0,%1,%2,%3}, {%4,%5,%6,%7}, {%8,%9}, {%0,%1,%2,%3};" \
    : "+f"((Cc)[0]),"+f"((Cc)[1]),"+f"((Cc)[2]),"+f"((Cc)[3]) \
    : "r"((Aa)[0]),"r"((Aa)[1]),"r"((Aa)[2]),"r"((Aa)[3]), "r"((Bb)[0]),"r"((Bb)[1]))

__device__ __forceinline__ uint32_t h2u(float a, float b) {
    __half2 t = __floats2half2_rn(a, b);
    return reinterpret_cast<uint32_t&>(t);
}

// ---------------- convert kernels --------------------------------------------
__global__ __launch_bounds__(256) void conv_x(const float* __restrict__ in,
                                              __half* __restrict__ oh)
{
    size_t base = ((size_t)blockIdx.x * 256 + threadIdx.x) * 4;
    float4 f = *(const float4*)(in + base);
    __half2 h2[2] = { __halves2half2(__float2half_rn(f.x), __float2half_rn(f.y)),
                      __halves2half2(__float2half_rn(f.z), __float2half_rn(f.w)) };
    *(uint2*)(oh + base) = *(uint2*)h2;
}

__global__ __launch_bounds__(256) void conv_w(const float* __restrict__ in,
                                              __half* __restrict__ oh, int K, int N)
{
    int t = blockIdx.x * 256 + threadIdx.x;
    if (t >= K * N) return;
    int k = t / N, n = t - k * N;
    oh[(size_t)n * K + k] = __float2half_rn(in[t]);   // W^T layout [n][k]
}

// ---------------- comb2 = fp16 padded (bias-gather + mask) --------------------
// layout [g][h][64 rows][56 cols]; pad cols 49.. = -20000 (masked), pad rows = 0
__global__ __launch_bounds__(256) void comb_k(const float* __restrict__ mask,
                                              const float* __restrict__ bias_table,
                                              const int* __restrict__ rel_index,
                                              __half* __restrict__ comb)
{
    int idx = blockIdx.x * 256 + threadIdx.x;
    const int total = NWG * NHEADS * 64 * 56;
    if (idx >= total) return;
    int c = idx % 56;
    int t = idx / 56;
    int r = t % 64;  t /= 64;
    int h = t % NHEADS;
    int g = t / NHEADS;
    float v;
    if (c >= SS)      v = -20000.f;
    else if (r >= SS) v = 0.f;
    else v = bias_table[rel_index[r * SS + c] * NHEADS + h] + mask[((size_t)g * SS + r) * SS + c];
    comb[idx] = __float2half_rn(v);
}

// ---------------- HMMA fp16 GEMM ----------------------------------------------
// C[M,N] = A[M,512] @ B[N,512]^T + bias (fp32 accum)
// out_mode 0: fp32 out; 1: fp16 out, cols<512 scaled by hd^-0.5 (q scaling)
#define STAGE_BYTES 32768
#define GEMM_SMEM   (3 * STAGE_BYTES)

__global__ __launch_bounds__(256) void gemm_hmma(
    const __half* __restrict__ Ahp, const __half* __restrict__ Bhp,
    const float* __restrict__ bias, void* __restrict__ Cv, int N, int out_mode)
{
    extern __shared__ char smem[];
    const uint32_t sb = smem_u32(smem);
    const int tid = threadIdx.x, wid = tid >> 5, lane = tid & 31;
    const int m0 = blockIdx.y * 128, n0 = blockIdx.x * 128;
    const int warp_m = wid & 1, warp_n = wid >> 1;

    float acc[4][4][4];
#pragma unroll
    for (int a = 0; a < 4; a++)
#pragma unroll
        for (int b = 0; b < 4; b++)
#pragma unroll
            for (int c = 0; c < 4; c++) acc[a][b][c] = 0.f;

    const int cr0 = tid >> 3;
    const int ckc = tid & 7;

#define LOAD_STAGE(st, ch) do {                                              \
        uint32_t sp_ = sb + (st) * STAGE_BYTES;                              \
        int kt_ = (ch) * 64;                                                 \
        _Pragma("unroll")                                                    \
        for (int u = 0; u < 4; u++) {                                        \
            int r_ = cr0 + u * 32;                                           \
            uint32_t d_ = sp_ + r_ * 128 + (((uint32_t)(ckc ^ (r_ & 7))) << 4); \
            size_t so_ = (size_t)kt_ + ckc * 8;                              \
            CP16(d_,         Ahp + (size_t)(m0 + r_) * KDIM + so_);          \
            CP16(d_ + 16384, Bhp + (size_t)(n0 + r_) * KDIM + so_);          \
        }                                                                    \
    } while (0)

    LOAD_STAGE(0, 0); CP_COMMIT();
    LOAD_STAGE(1, 1); CP_COMMIT();

    const int g  = lane >> 3;
    const int lr = lane & 7;
    const int gh = g >> 1;
    const int lrB = lane & 7, hB = (lane >> 3) & 1;
    const uint32_t aRow = (uint32_t)((warp_m * 64 + (g & 1) * 8 + lr) * 128);
    const uint32_t bRow = (uint32_t)((warp_n * 32 + lrB) * 128);

    for (int c = 0; c < 8; c++) {
        if (c < 7) CP_WAIT1(); else CP_WAIT0();
        __syncthreads();
        if (c + 2 < 8) { LOAD_STAGE((c + 2) % 3, c + 2); CP_COMMIT(); }

        const uint32_t As = sb + (c % 3) * STAGE_BYTES;
        const uint32_t Bs = As + 16384;
#pragma unroll
        for (int ks = 0; ks < 4; ks++) {
            uint32_t ah[4][4], bh[4][2];
            const uint32_t cA = (uint32_t)(((ks * 2 + gh) ^ lr) << 4);
            const uint32_t cB = (uint32_t)(((ks * 2 + hB) ^ lrB) << 4);
#pragma unroll
            for (int mi = 0; mi < 4; mi++) LDSM4(ah[mi], As + aRow + mi * 2048 + cA);
#pragma unroll
            for (int ni = 0; ni < 4; ni++) LDSM2(bh[ni], Bs + bRow + ni * 1024 + cB);
#pragma unroll
            for (int mi = 0; mi < 4; mi++)
#pragma unroll
                for (int ni = 0; ni < 4; ni++) MMA16816(acc[mi][ni], ah[mi], bh[ni]);
        }
    }

    const int rbase = m0 + warp_m * 64 + (lane >> 2);
    const int cbase = n0 + warp_n * 32 + (lane & 3) * 2;
    if (out_mode == 0) {
        float* C = (float*)Cv;
#pragma unroll
        for (int mi = 0; mi < 4; mi++)
#pragma unroll
            for (int ni = 0; ni < 4; ni++) {
                int cc = cbase + ni * 8;
                float b0 = bias[cc], b1 = bias[cc + 1];
                int r0 = rbase + mi * 16;
                *(float2*)(C + (size_t)r0 * N + cc) =
                    make_float2(acc[mi][ni][0] + b0, acc[mi][ni][1] + b1);
                *(float2*)(C + (size_t)(r0 + 8) * N + cc) =
                    make_float2(acc[mi][ni][2] + b0, acc[mi][ni][3] + b1);
            }
    } else {
        __half* C = (__half*)Cv;
        const float s = (n0 < 512) ? 0.17677669529663687f : 1.0f;
#pragma unroll
        for (int mi = 0; mi < 4; mi++)
#pragma unroll
            for (int ni = 0; ni < 4; ni++) {
                int cc = cbase + ni * 8;
                float b0 = bias[cc], b1 = bias[cc + 1];
                int r0 = rbase + mi * 16;
                __half2 w0 = __floats2half2_rn((acc[mi][ni][0] + b0) * s, (acc[mi][ni][1] + b1) * s);
                __half2 w1 = __floats2half2_rn((acc[mi][ni][2] + b0) * s, (acc[mi][ni][3] + b1) * s);
                *(__half2*)(C + (size_t)r0 * N + cc) = w0;
                *(__half2*)(C + (size_t)(r0 + 8) * N + cc) = w1;
            }
    }
#undef LOAD_STAGE
}

// ---------------- tensor-core fused window attention --------------------------
// block: one window x 2 heads; 8 warps; warp = (head hh, m-tile mi)
__global__ __launch_bounds__(256) void attn_tc(
    const __half* __restrict__ qkv, const __half* __restrict__ comb2,
    __half* __restrict__ outh)
{
    __shared__ __align__(16) __half sQ[2][64][40];
    __shared__ __align__(16) __half sK[2][64][40];
    __shared__ __align__(16) __half sVt[2][32][72];

    const int b = blockIdx.x;
    const int h0 = blockIdx.y * 2;
    const int tid = threadIdx.x;
    const int lane = tid & 31, wid = tid >> 5;

    // load Q, K [64 rows pad][32] fp16
#pragma unroll
    for (int u = 0; u < 32; u++) {             // 2 heads * 2 mats * 64 * 32 / 256
        int i = tid + u * 256;
        int d = i & 31, row = (i >> 5) & 63, mat = (i >> 11) & 1, hh = i >> 12;
        __half v = __ushort_as_half((unsigned short)0);
        if (row < SS)
            v = qkv[(size_t)(b * SS + row) * QKV_N + mat * 512 + (h0 + hh) * HD + d];
        if (mat == 0) sQ[hh][row][d] = v; else sK[hh][row][d] = v;
    }
    // load V transposed: sVt[hh][dim][token]
#pragma unroll
    for (int u = 0; u < 16; u++) {             // 2 * 64 * 32 / 256
        int i = tid + u * 256;
        int d = i & 31, row = (i >> 5) & 63, hh = i >> 11;
        __half v = __ushort_as_half((unsigned short)0);
        if (row < SS)
            v = qkv[(size_t)(b * SS + row) * QKV_N + 1024 + (h0 + hh) * HD + d];
        sVt[hh][d][row] = v;
    }
    __syncthreads();

    const int hh = wid >> 2;
    const int mi = wid & 3;
    const int h  = h0 + hh;
    const int lr = lane & 7;
    const int grp = lane >> 3;
    const int khalf = (lane >> 3) & 1;

    // Q A-fragments (2 k16 tiles)
    uint32_t aq[2][4];
    {
        int arow = mi * 16 + (grp & 1) * 8 + lr;
        int acol = (grp >> 1) * 8;
        LDSM4(aq[0], smem_u32(&sQ[hh][arow][acol]));
        LDSM4(aq[1], smem_u32(&sQ[hh][arow][16 + acol]));
    }

    // S = Q K^T  (7 n-tiles)
    float sacc[7][4];
#pragma unroll
    for (int n = 0; n < 7; n++)
#pragma unroll
        for (int e = 0; e < 4; e++) sacc[n][e] = 0.f;

#pragma unroll
    for (int n = 0; n < 7; n++) {
        int brow = n * 8 + lr;
#pragma unroll
        for (int kt = 0; kt < 2; kt++) {
            uint32_t bk[2];
            LDSM2(bk, smem_u32(&sK[hh][brow][kt * 16 + khalf * 8]));
            MMA16816(sacc[n], aq[kt], bk);
        }
    }

    // softmax (no max-subtraction; comb pads force exp->0 on pad cols)
    const int wg = b & (NWG - 1);
    const __half* cbp = comb2 + (size_t)(wg * NHEADS + h) * 64 * 56;
    const int r0 = mi * 16 + (lane >> 2);
    const int c0 = (lane & 3) * 2;
    float rs0 = 0.f, rs1 = 0.f;
#pragma unroll
    for (int n = 0; n < 7; n++) {
        __half2 cv0 = *(const __half2*)(cbp + r0 * 56 + n * 8 + c0);
        __half2 cv1 = *(const __half2*)(cbp + (r0 + 8) * 56 + n * 8 + c0);
        float2 f0 = __half22float2(cv0), f1 = __half22float2(cv1);
        sacc[n][0] = __expf(sacc[n][0] + f0.x);
        sacc[n][1] = __expf(sacc[n][1] + f0.y);
        sacc[n][2] = __expf(sacc[n][2] + f1.x);
        sacc[n][3] = __expf(sacc[n][3] + f1.y);
        rs0 += sacc[n][0] + sacc[n][1];
        rs1 += sacc[n][2] + sacc[n][3];
    }
    rs0 += __shfl_xor_sync(0xffffffffu, rs0, 1);
    rs0 += __shfl_xor_sync(0xffffffffu, rs0, 2);
    rs1 += __shfl_xor_sync(0xffffffffu, rs1, 1);
    rs1 += __shfl_xor_sync(0xffffffffu, rs1, 2);
    const float inv0 = 1.f / (rs0 + 1e-30f);
    const float inv1 = 1.f / (rs1 + 1e-30f);

    // P -> A fragments (acc-pair = A m16k16 identity; tile 7 is zero)
    uint32_t pa[4][4];
#pragma unroll
    for (int t = 0; t < 3; t++) {
        pa[t][0] = h2u(sacc[2 * t][0] * inv0, sacc[2 * t][1] * inv0);
        pa[t][1] = h2u(sacc[2 * t][2] * inv1, sacc[2 * t][3] * inv1);
        pa[t][2] = h2u(sacc[2 * t + 1][0] * inv0, sacc[2 * t + 1][1] * inv0);
        pa[t][3] = h2u(sacc[2 * t + 1][2] * inv1, sacc[2 * t + 1][3] * inv1);
    }
    pa[3][0] = h2u(sacc[6][0] * inv0, sacc[6][1] * inv0);
    pa[3][1] = h2u(sacc[6][2] * inv1, sacc[6][3] * inv1);
    pa[3][2] = 0u;
    pa[3][3] = 0u;

    // O = P V   (V from transposed smem; B pattern identical to GEMM)
    float oacc[4][4];
#pragma unroll
    for (int nv = 0; nv < 4; nv++)
#pragma unroll
        for (int e = 0; e < 4; e++) oacc[nv][e] = 0.f;

#pragma unroll
    for (int t = 0; t < 4; t++)
#pragma unroll
        for (int nv = 0; nv < 4; nv++) {
            uint32_t bv[2];
            LDSM2(bv, smem_u32(&sVt[hh][nv * 8 + lr][t * 16 + khalf * 8]));
            MMA16816(oacc[nv], pa[t], bv);
        }

    // store fp16 rows < 49
#pragma unroll
    for (int nv = 0; nv < 4; nv++) {
        int col = h * HD + nv * 8 + c0;
        if (r0 < SS) {
            __half2 w = __floats2half2_rn(oacc[nv][0], oacc[nv][1]);
            *(__half2*)(outh + (size_t)(b * SS + r0) * DIMC + col) = w;
        }
        if (r0 + 8 < SS) {
            __half2 w = __floats2half2_rn(oacc[nv][2], oacc[nv][3]);
            *(__half2*)(outh + (size_t)(b * SS + r0 + 8) * DIMC + col) = w;
        }
    }
}

// ---------------- launch ------------------------------------------------------
extern "C" void kernel_launch(void* const* d_in, const int* in_sizes, int n_in,
                              void* d_out, int out_size)
{
    const float* x          = (const float*)d_in[0];
    const float* mask       = (const float*)d_in[1];
    const float* Wqkv       = (const float*)d_in[2];
    const float* bqkv       = (const float*)d_in[3];
    const float* Wproj      = (const float*)d_in[4];
    const float* bproj      = (const float*)d_in[5];
    const float* bias_table = (const float*)d_in[6];
    const int*   rel_index  = (const int*)d_in[7];
    float* out = (float*)d_out;

    __half *qkvh, *xh, *wqh, *wph, *comb2;
    cudaGetSymbolAddress((void**)&qkvh,  g_qkvh);
    cudaGetSymbolAddress((void**)&xh,    g_xh);
    cudaGetSymbolAddress((void**)&wqh,   g_wqh);
    cudaGetSymbolAddress((void**)&wph,   g_wph);
    cudaGetSymbolAddress((void**)&comb2, g_comb2);

    cudaFuncSetAttribute(gemm_hmma, cudaFuncAttributeMaxDynamicSharedMemorySize, GEMM_SMEM);

    conv_x<<<(size_t)TOKENS * KDIM / 1024, 256>>>(x, xh);
    conv_w<<<(KDIM * QKV_N + 255) / 256, 256>>>(Wqkv, wqh, KDIM, QKV_N);
    conv_w<<<(KDIM * DIMC  + 255) / 256, 256>>>(Wproj, wph, KDIM, DIMC);
    comb_k<<<(NWG * NHEADS * 64 * 56 + 255) / 256, 256>>>(mask, bias_table, rel_index, comb2);

    gemm_hmma<<<dim3(QKV_N / 128, TOKENS / 128), 256, GEMM_SMEM>>>(
        xh, wqh, bqkv, qkvh, QKV_N, 1);

    attn_tc<<<dim3(4096, 8), 256>>>(qkvh, comb2, xh);

    gemm_hmma<<<dim3(DIMC / 128, TOKENS / 128), 256, GEMM_SMEM>>>(
        xh, wph, bproj, out, DIMC, 0);
}

// round 11
// speedup vs baseline: 10.1401x; 1.1341x over previous
#include <cuda_runtime.h>
#include <cuda_fp16.h>
#include <cstdint>

#define TOKENS   200704      // 4096 * 49
#define DIMC     512
#define QKV_N    1536
#define KDIM     512
#define SS       49
#define NHEADS   16
#define HD       32
#define NWG      64

// ---------------- scratch ---------------------------------------------------
__device__ __half g_qkvh[(size_t)TOKENS * QKV_N];    // 617 MB fp16 qkv
__device__ __half g_xh[(size_t)TOKENS * KDIM];       // fp16 activations (reused for attn out)
__device__ __half g_wqh[(size_t)QKV_N * KDIM];       // Wqkv^T fp16
__device__ __half g_wph[(size_t)DIMC * KDIM];        // Wproj^T fp16
__device__ __half g_comb2[(size_t)NWG * NHEADS * 64 * 56];  // bias+mask fp16, padded

// ---------------- asm helpers -----------------------------------------------
__device__ __forceinline__ uint32_t smem_u32(const void* p) {
    uint32_t a;
    asm("{ .reg .u64 t; cvta.to.shared.u64 t, %1; cvt.u32.u64 %0, t; }" : "=r"(a) : "l"(p));
    return a;
}

#define CP16(d, s) asm volatile("cp.async.cg.shared.global [%0], [%1], 16;" :: "r"(d), "l"(s))
#define CP_COMMIT() asm volatile("cp.async.commit_group;" ::: "memory")
#define CP_WAIT2()  asm volatile("cp.async.wait_group 2;" ::: "memory")
#define CP_WAIT1()  asm volatile("cp.async.wait_group 1;" ::: "memory")
#define CP_WAIT0()  asm volatile("cp.async.wait_group 0;" ::: "memory")

#define LDSM4(R, a) asm volatile( \
    "ldmatrix.sync.aligned.m8n8.x4.shared.b16 {%0,%1,%2,%3}, [%4];" \
    : "=r"((R)[0]),"=r"((R)[1]),"=r"((R)[2]),"=r"((R)[3]) : "r"(a))
#define LDSM2(R, a) asm volatile( \
    "ldmatrix.sync.aligned.m8n8.x2.shared.b16 {%0,%1}, [%2];" \
    : "=r"((R)[0]),"=r"((R)[1]) : "r"(a))

#define MMA16816(Cc, Aa, Bb) asm volatile( \
    "mma.sync.aligned.m16n8k16.row.col.f32.f16.f16.f32 " \
    "{%0,%1,%2,%3}, {%4,%5,%6,%7}, {%8,%9}, {%0,%1,%2,%3};" \
    : "+f"((Cc)[0]),"+f"((Cc)[1]),"+f"((Cc)[2]),"+f"((Cc)[3]) \
    : "r"((Aa)[0]),"r"((Aa)[1]),"r"((Aa)[2]),"r"((Aa)[3]), "r"((Bb)[0]),"r"((Bb)[1]))

__device__ __forceinline__ uint32_t h2u(float a, float b) {
    __half2 t = __floats2half2_rn(a, b);
    return reinterpret_cast<uint32_t&>(t);
}

// ---------------- convert kernels --------------------------------------------
__global__ __launch_bounds__(256) void conv_x(const float* __restrict__ in,
                                              __half* __restrict__ oh)
{
    size_t base = ((size_t)blockIdx.x * 256 + threadIdx.x) * 4;
    float4 f = *(const float4*)(in + base);
    __half2 h2[2] = { __halves2half2(__float2half_rn(f.x), __float2half_rn(f.y)),
                      __halves2half2(__float2half_rn(f.z), __float2half_rn(f.w)) };
    *(uint2*)(oh + base) = *(uint2*)h2;
}

__global__ __launch_bounds__(256) void conv_w(const float* __restrict__ in,
                                              __half* __restrict__ oh, int K, int N)
{
    int t = blockIdx.x * 256 + threadIdx.x;
    if (t >= K * N) return;
    int k = t / N, n = t - k * N;
    oh[(size_t)n * K + k] = __float2half_rn(in[t]);   // W^T layout [n][k]
}

// ---------------- comb2 = fp16 padded (bias-gather + mask) --------------------
__global__ __launch_bounds__(256) void comb_k(const float* __restrict__ mask,
                                              const float* __restrict__ bias_table,
                                              const int* __restrict__ rel_index,
                                              __half* __restrict__ comb)
{
    int idx = blockIdx.x * 256 + threadIdx.x;
    const int total = NWG * NHEADS * 64 * 56;
    if (idx >= total) return;
    int c = idx % 56;
    int t = idx / 56;
    int r = t % 64;  t /= 64;
    int h = t % NHEADS;
    int g = t / NHEADS;
    float v;
    if (c >= SS)      v = -20000.f;
    else if (r >= SS) v = 0.f;
    else v = bias_table[rel_index[r * SS + c] * NHEADS + h] + mask[((size_t)g * SS + r) * SS + c];
    comb[idx] = __float2half_rn(v);
}

// ---------------- HMMA fp16 GEMM ----------------------------------------------
// C[M,N] = A[M,512] @ B[N,512]^T + bias (fp32 accum)
// Block 128x256, warp tile 64x64 (2x4 warp grid), BK=64, 4-stage cp.async.
// out_mode 0: fp32 out; 1: fp16 out, cols<512 scaled by hd^-0.5 (q scaling)
#define STAGE_BYTES 49152          // A 16 KB + B 32 KB
#define GEMM_SMEM   (4 * STAGE_BYTES)

__global__ __launch_bounds__(256, 1) void gemm_hmma(
    const __half* __restrict__ Ahp, const __half* __restrict__ Bhp,
    const float* __restrict__ bias, void* __restrict__ Cv, int N, int out_mode)
{
    extern __shared__ char smem[];
    const uint32_t sb = smem_u32(smem);
    const int tid = threadIdx.x, wid = tid >> 5, lane = tid & 31;
    const int m0 = blockIdx.y * 128, n0 = blockIdx.x * 256;
    const int warp_m = wid & 1, warp_n = wid >> 1;

    float acc[4][8][4];
#pragma unroll
    for (int a = 0; a < 4; a++)
#pragma unroll
        for (int b = 0; b < 8; b++)
#pragma unroll
            for (int c = 0; c < 4; c++) acc[a][b][c] = 0.f;

    const int cr0 = tid >> 3;        // 0..31
    const int ckc = tid & 7;         // 16B chunk within 128B row

#define LOAD_STAGE(st, ch) do {                                              \
        uint32_t sp_ = sb + (st) * STAGE_BYTES;                              \
        int kt_ = (ch) * 64;                                                 \
        size_t so_ = (size_t)kt_ + ckc * 8;                                  \
        _Pragma("unroll")                                                    \
        for (int u = 0; u < 4; u++) {                                        \
            int r_ = cr0 + u * 32;                                           \
            uint32_t d_ = sp_ + r_ * 128 + (((uint32_t)(ckc ^ (r_ & 7))) << 4); \
            CP16(d_, Ahp + (size_t)(m0 + r_) * KDIM + so_);                  \
        }                                                                    \
        _Pragma("unroll")                                                    \
        for (int u = 0; u < 8; u++) {                                        \
            int r_ = cr0 + u * 32;                                           \
            uint32_t d_ = sp_ + 16384 + r_ * 128 + (((uint32_t)(ckc ^ (r_ & 7))) << 4); \
            CP16(d_, Bhp + (size_t)(n0 + r_) * KDIM + so_);                  \
        }                                                                    \
    } while (0)

    LOAD_STAGE(0, 0); CP_COMMIT();
    LOAD_STAGE(1, 1); CP_COMMIT();
    LOAD_STAGE(2, 2); CP_COMMIT();

    const int g  = lane >> 3;
    const int lr = lane & 7;
    const int gh = g >> 1;
    const int lrB = lane & 7, hB = (lane >> 3) & 1;
    const uint32_t aRow = (uint32_t)((warp_m * 64 + (g & 1) * 8 + lr) * 128);
    const uint32_t bRow = (uint32_t)((warp_n * 64 + lrB) * 128);

    for (int c = 0; c < 8; c++) {
        if (c < 6) CP_WAIT2(); else if (c == 6) CP_WAIT1(); else CP_WAIT0();
        __syncthreads();
        if (c + 3 < 8) { LOAD_STAGE((c + 3) & 3, c + 3); CP_COMMIT(); }

        const uint32_t As = sb + (c & 3) * STAGE_BYTES;
        const uint32_t Bs = As + 16384;
#pragma unroll
        for (int ks = 0; ks < 4; ks++) {
            uint32_t ah[4][4], bh[8][2];
            const uint32_t cA = (uint32_t)(((ks * 2 + gh) ^ lr) << 4);
            const uint32_t cB = (uint32_t)(((ks * 2 + hB) ^ lrB) << 4);
#pragma unroll
            for (int mi = 0; mi < 4; mi++) LDSM4(ah[mi], As + aRow + mi * 2048 + cA);
#pragma unroll
            for (int ni = 0; ni < 8; ni++) LDSM2(bh[ni], Bs + bRow + ni * 1024 + cB);
#pragma unroll
            for (int mi = 0; mi < 4; mi++)
#pragma unroll
                for (int ni = 0; ni < 8; ni++) MMA16816(acc[mi][ni], ah[mi], bh[ni]);
        }
    }

    const int rbase = m0 + warp_m * 64 + (lane >> 2);
    const int cbase = n0 + warp_n * 64 + (lane & 3) * 2;
    if (out_mode == 0) {
        float* C = (float*)Cv;
#pragma unroll
        for (int mi = 0; mi < 4; mi++)
#pragma unroll
            for (int ni = 0; ni < 8; ni++) {
                int cc = cbase + ni * 8;
                float b0 = bias[cc], b1 = bias[cc + 1];
                int r0 = rbase + mi * 16;
                *(float2*)(C + (size_t)r0 * N + cc) =
                    make_float2(acc[mi][ni][0] + b0, acc[mi][ni][1] + b1);
                *(float2*)(C + (size_t)(r0 + 8) * N + cc) =
                    make_float2(acc[mi][ni][2] + b0, acc[mi][ni][3] + b1);
            }
    } else {
        __half* C = (__half*)Cv;
#pragma unroll
        for (int mi = 0; mi < 4; mi++)
#pragma unroll
            for (int ni = 0; ni < 8; ni++) {
                int cc = cbase + ni * 8;
                const float s = (cc < 512) ? 0.17677669529663687f : 1.0f;
                float b0 = bias[cc], b1 = bias[cc + 1];
                int r0 = rbase + mi * 16;
                __half2 w0 = __floats2half2_rn((acc[mi][ni][0] + b0) * s, (acc[mi][ni][1] + b1) * s);
                __half2 w1 = __floats2half2_rn((acc[mi][ni][2] + b0) * s, (acc[mi][ni][3] + b1) * s);
                *(__half2*)(C + (size_t)r0 * N + cc) = w0;
                *(__half2*)(C + (size_t)(r0 + 8) * N + cc) = w1;
            }
    }
#undef LOAD_STAGE
}

// ---------------- tensor-core fused window attention --------------------------
// block: one window x 2 heads; 8 warps; warp = (head hh, m-tile mi)
__global__ __launch_bounds__(256) void attn_tc(
    const __half* __restrict__ qkv, const __half* __restrict__ comb2,
    __half* __restrict__ outh)
{
    __shared__ __align__(16) __half sQ[2][64][40];
    __shared__ __align__(16) __half sK[2][64][40];
    __shared__ __align__(16) __half sVt[2][32][72];

    const int b = blockIdx.x;
    const int h0 = blockIdx.y * 2;
    const int tid = threadIdx.x;
    const int lane = tid & 31, wid = tid >> 5;

    const __half2 zero2 = __halves2half2(__ushort_as_half(0), __ushort_as_half(0));

    // load Q, K [64 rows pad][32] fp16 as half2
#pragma unroll
    for (int u = 0; u < 16; u++) {             // 2 heads * 2 mats * 64 * 16 half2 / 256
        int i = tid + u * 256;
        int d2 = i & 15, row = (i >> 4) & 63, mat = (i >> 10) & 1, hh = i >> 11;
        __half2 v = zero2;
        if (row < SS)
            v = *(const __half2*)(qkv + (size_t)(b * SS + row) * QKV_N
                                  + mat * 512 + (h0 + hh) * HD + d2 * 2);
        if (mat == 0) *(__half2*)&sQ[hh][row][d2 * 2] = v;
        else          *(__half2*)&sK[hh][row][d2 * 2] = v;
    }
    // load V transposed: sVt[hh][dim][token]
#pragma unroll
    for (int u = 0; u < 8; u++) {              // 2 * 64 * 16 half2 / 256
        int i = tid + u * 256;
        int d2 = i & 15, row = (i >> 4) & 63, hh = i >> 10;
        __half2 v = zero2;
        if (row < SS)
            v = *(const __half2*)(qkv + (size_t)(b * SS + row) * QKV_N
                                  + 1024 + (h0 + hh) * HD + d2 * 2);
        sVt[hh][d2 * 2][row]     = __low2half(v);
        sVt[hh][d2 * 2 + 1][row] = __high2half(v);
    }
    __syncthreads();

    const int hh = wid >> 2;
    const int mi = wid & 3;
    const int h  = h0 + hh;
    const int lr = lane & 7;
    const int grp = lane >> 3;
    const int khalf = (lane >> 3) & 1;

    // Q A-fragments (2 k16 tiles)
    uint32_t aq[2][4];
    {
        int arow = mi * 16 + (grp & 1) * 8 + lr;
        int acol = (grp >> 1) * 8;
        LDSM4(aq[0], smem_u32(&sQ[hh][arow][acol]));
        LDSM4(aq[1], smem_u32(&sQ[hh][arow][16 + acol]));
    }

    // S = Q K^T  (7 n-tiles)
    float sacc[7][4];
#pragma unroll
    for (int n = 0; n < 7; n++)
#pragma unroll
        for (int e = 0; e < 4; e++) sacc[n][e] = 0.f;

#pragma unroll
    for (int n = 0; n < 7; n++) {
        int brow = n * 8 + lr;
#pragma unroll
        for (int kt = 0; kt < 2; kt++) {
            uint32_t bk[2];
            LDSM2(bk, smem_u32(&sK[hh][brow][kt * 16 + khalf * 8]));
            MMA16816(sacc[n], aq[kt], bk);
        }
    }

    // softmax (no max-subtraction; comb pads force exp->0 on pad cols)
    const int wg = b & (NWG - 1);
    const __half* cbp = comb2 + (size_t)(wg * NHEADS + h) * 64 * 56;
    const int r0 = mi * 16 + (lane >> 2);
    const int c0 = (lane & 3) * 2;
    float rs0 = 0.f, rs1 = 0.f;
#pragma unroll
    for (int n = 0; n < 7; n++) {
        __half2 cv0 = *(const __half2*)(cbp + r0 * 56 + n * 8 + c0);
        __half2 cv1 = *(const __half2*)(cbp + (r0 + 8) * 56 + n * 8 + c0);
        float2 f0 = __half22float2(cv0), f1 = __half22float2(cv1);
        sacc[n][0] = __expf(sacc[n][0] + f0.x);
        sacc[n][1] = __expf(sacc[n][1] + f0.y);
        sacc[n][2] = __expf(sacc[n][2] + f1.x);
        sacc[n][3] = __expf(sacc[n][3] + f1.y);
        rs0 += sacc[n][0] + sacc[n][1];
        rs1 += sacc[n][2] + sacc[n][3];
    }
    rs0 += __shfl_xor_sync(0xffffffffu, rs0, 1);
    rs0 += __shfl_xor_sync(0xffffffffu, rs0, 2);
    rs1 += __shfl_xor_sync(0xffffffffu, rs1, 1);
    rs1 += __shfl_xor_sync(0xffffffffu, rs1, 2);
    const float inv0 = 1.f / (rs0 + 1e-30f);
    const float inv1 = 1.f / (rs1 + 1e-30f);

    // P -> A fragments (acc-pair = A m16k16 identity; tile 7 is zero)
    uint32_t pa[4][4];
#pragma unroll
    for (int t = 0; t < 3; t++) {
        pa[t][0] = h2u(sacc[2 * t][0] * inv0, sacc[2 * t][1] * inv0);
        pa[t][1] = h2u(sacc[2 * t][2] * inv1, sacc[2 * t][3] * inv1);
        pa[t][2] = h2u(sacc[2 * t + 1][0] * inv0, sacc[2 * t + 1][1] * inv0);
        pa[t][3] = h2u(sacc[2 * t + 1][2] * inv1, sacc[2 * t + 1][3] * inv1);
    }
    pa[3][0] = h2u(sacc[6][0] * inv0, sacc[6][1] * inv0);
    pa[3][1] = h2u(sacc[6][2] * inv1, sacc[6][3] * inv1);
    pa[3][2] = 0u;
    pa[3][3] = 0u;

    // O = P V   (V from transposed smem; B pattern identical to GEMM)
    float oacc[4][4];
#pragma unroll
    for (int nv = 0; nv < 4; nv++)
#pragma unroll
        for (int e = 0; e < 4; e++) oacc[nv][e] = 0.f;

#pragma unroll
    for (int t = 0; t < 4; t++)
#pragma unroll
        for (int nv = 0; nv < 4; nv++) {
            uint32_t bv[2];
            LDSM2(bv, smem_u32(&sVt[hh][nv * 8 + lr][t * 16 + khalf * 8]));
            MMA16816(oacc[nv], pa[t], bv);
        }

    // store fp16 rows < 49
#pragma unroll
    for (int nv = 0; nv < 4; nv++) {
        int col = h * HD + nv * 8 + c0;
        if (r0 < SS) {
            __half2 w = __floats2half2_rn(oacc[nv][0], oacc[nv][1]);
            *(__half2*)(outh + (size_t)(b * SS + r0) * DIMC + col) = w;
        }
        if (r0 + 8 < SS) {
            __half2 w = __floats2half2_rn(oacc[nv][2], oacc[nv][3]);
            *(__half2*)(outh + (size_t)(b * SS + r0 + 8) * DIMC + col) = w;
        }
    }
}

// ---------------- launch ------------------------------------------------------
extern "C" void kernel_launch(void* const* d_in, const int* in_sizes, int n_in,
                              void* d_out, int out_size)
{
    const float* x          = (const float*)d_in[0];
    const float* mask       = (const float*)d_in[1];
    const float* Wqkv       = (const float*)d_in[2];
    const float* bqkv       = (const float*)d_in[3];
    const float* Wproj      = (const float*)d_in[4];
    const float* bproj      = (const float*)d_in[5];
    const float* bias_table = (const float*)d_in[6];
    const int*   rel_index  = (const int*)d_in[7];
    float* out = (float*)d_out;

    __half *qkvh, *xh, *wqh, *wph, *comb2;
    cudaGetSymbolAddress((void**)&qkvh,  g_qkvh);
    cudaGetSymbolAddress((void**)&xh,    g_xh);
    cudaGetSymbolAddress((void**)&wqh,   g_wqh);
    cudaGetSymbolAddress((void**)&wph,   g_wph);
    cudaGetSymbolAddress((void**)&comb2, g_comb2);

    cudaFuncSetAttribute(gemm_hmma, cudaFuncAttributeMaxDynamicSharedMemorySize, GEMM_SMEM);

    conv_x<<<(size_t)TOKENS * KDIM / 1024, 256>>>(x, xh);
    conv_w<<<(KDIM * QKV_N + 255) / 256, 256>>>(Wqkv, wqh, KDIM, QKV_N);
    conv_w<<<(KDIM * DIMC  + 255) / 256, 256>>>(Wproj, wph, KDIM, DIMC);
    comb_k<<<(NWG * NHEADS * 64 * 56 + 255) / 256, 256>>>(mask, bias_table, rel_index, comb2);

    gemm_hmma<<<dim3(QKV_N / 256, TOKENS / 128), 256, GEMM_SMEM>>>(
        xh, wqh, bqkv, qkvh, QKV_N, 1);

    attn_tc<<<dim3(4096, 8), 256>>>(qkvh, comb2, xh);

    gemm_hmma<<<dim3(DIMC / 256, TOKENS / 128), 256, GEMM_SMEM>>>(
        xh, wph, bproj, out, DIMC, 0);
}